// round 14
// baseline (speedup 1.0000x reference)
#include <cuda_runtime.h>
#include <cuda_bf16.h>
#include <math.h>
#include <stdint.h>

#define Bsz 2
#define Ssz 2048
#define Dsz 1024
#define Hsz 16
#define DHsz 64
#define FFsz 4096
#define Mrows (Bsz*Ssz)   // 4096
#define BH    (Bsz*Hsz)   // 32

typedef __nv_bfloat16 bf16;

// ---------------- scratch (device globals) ----------------------------------
__device__ bf16  g_hhi[Mrows * Dsz];
__device__ bf16  g_hlo[Mrows * Dsz];
__device__ bf16  g_midhi[(size_t)Mrows * FFsz];
__device__ bf16  g_midlo[(size_t)Mrows * FFsz];
__device__ bf16  g_wqkvT_hi[3 * Dsz * Dsz];
__device__ bf16  g_wqkvT_lo[3 * Dsz * Dsz];
__device__ bf16  g_w1T_hi[FFsz * Dsz];
__device__ bf16  g_w1T_lo[FFsz * Dsz];
__device__ bf16  g_w2T_hi[Dsz * FFsz];
__device__ bf16  g_w2T_lo[Dsz * FFsz];
__device__ bf16  g_qh[BH * Ssz * DHsz];
__device__ bf16  g_ql[BH * Ssz * DHsz];
__device__ bf16  g_kh[BH * Ssz * DHsz];
__device__ bf16  g_kl[BH * Ssz * DHsz];
__device__ bf16  g_vth[BH * DHsz * Ssz];   // transposed: [bh][dh][s]
__device__ bf16  g_vtl[BH * DHsz * Ssz];

// ---------------- PTX helpers -------------------------------------------------
__device__ __forceinline__ uint32_t smem_u32(const void* p) {
    uint32_t a;
    asm("{ .reg .u64 t; cvta.to.shared.u64 t, %1; cvt.u32.u64 %0, t; }" : "=r"(a) : "l"(p));
    return a;
}
__device__ __forceinline__ void cp16(uint32_t dst, const void* src) {
    asm volatile("cp.async.cg.shared.global [%0], [%1], 16;" :: "r"(dst), "l"(src));
}
__device__ __forceinline__ void cp_commit() { asm volatile("cp.async.commit_group;"); }
__device__ __forceinline__ void cp_wait1()  { asm volatile("cp.async.wait_group 1;" ::: "memory"); }
__device__ __forceinline__ void cp_wait0()  { asm volatile("cp.async.wait_group 0;" ::: "memory"); }

__device__ __forceinline__ void ldsm4(uint32_t* r, uint32_t addr) {
    asm volatile("ldmatrix.sync.aligned.m8n8.x4.shared.b16 {%0,%1,%2,%3}, [%4];"
        : "=r"(r[0]), "=r"(r[1]), "=r"(r[2]), "=r"(r[3]) : "r"(addr));
}
// Non-volatile — pure register op; lets ptxas interleave MMAs with ldsm.
__device__ __forceinline__ void mma_bf16(float* d, const uint32_t* a, const uint32_t* b) {
    asm("mma.sync.aligned.m16n8k16.row.col.f32.bf16.bf16.f32 "
        "{%0,%1,%2,%3}, {%4,%5,%6,%7}, {%8,%9}, {%0,%1,%2,%3};"
        : "+f"(d[0]), "+f"(d[1]), "+f"(d[2]), "+f"(d[3])
        : "r"(a[0]), "r"(a[1]), "r"(a[2]), "r"(a[3]), "r"(b[0]), "r"(b[1]));
}

__device__ __forceinline__ float gelu_exact(float v) {
    return 0.5f * v * (1.0f + erff(v * 0.70710678118654752f));
}
struct __align__(8) bf4 { bf16 a, b, c, d; };
struct __align__(4) bf2 { bf16 a, b; };

__device__ __forceinline__ uint32_t packbf2(float a, float b) {
    __nv_bfloat162 t = __float22bfloat162_rn(make_float2(a, b));
    return *(uint32_t*)&t;
}

// ---------------- LayerNorm -> bf16 hi/lo split -------------------------------
__global__ void __launch_bounds__(256) ln_split(const float* __restrict__ x,
                                                const float* __restrict__ g,
                                                const float* __restrict__ beta,
                                                bf16* __restrict__ hi,
                                                bf16* __restrict__ lo)
{
    int row = blockIdx.x;
    int t   = threadIdx.x;
    float4 xv = ((const float4*)(x + (size_t)row * Dsz))[t];
    float s  = xv.x + xv.y + xv.z + xv.w;
    float ss = xv.x*xv.x + xv.y*xv.y + xv.z*xv.z + xv.w*xv.w;
    #pragma unroll
    for (int o = 16; o; o >>= 1) {
        s  += __shfl_xor_sync(0xffffffffu, s,  o);
        ss += __shfl_xor_sync(0xffffffffu, ss, o);
    }
    __shared__ float sh[16];
    int w = t >> 5;
    if ((t & 31) == 0) { sh[w] = s; sh[8 + w] = ss; }
    __syncthreads();
    s = 0.f; ss = 0.f;
    #pragma unroll
    for (int i = 0; i < 8; i++) { s += sh[i]; ss += sh[8 + i]; }
    float mu  = s * (1.0f / Dsz);
    float var = ss * (1.0f / Dsz) - mu * mu;
    float inv = rsqrtf(var + 1e-5f);
    float4 gv = ((const float4*)g)[t];
    float4 bv = ((const float4*)beta)[t];
    float r[4];
    r[0] = (xv.x - mu) * inv * gv.x + bv.x;
    r[1] = (xv.y - mu) * inv * gv.y + bv.y;
    r[2] = (xv.z - mu) * inv * gv.z + bv.z;
    r[3] = (xv.w - mu) * inv * gv.w + bv.w;
    bf16 h4[4], l4[4];
    #pragma unroll
    for (int i = 0; i < 4; i++) {
        h4[i] = __float2bfloat16_rn(r[i]);
        l4[i] = __float2bfloat16_rn(r[i] - __bfloat162float(h4[i]));
    }
    size_t off = (size_t)row * Dsz + t * 4;
    *(bf4*)(hi + off) = bf4{h4[0], h4[1], h4[2], h4[3]};
    *(bf4*)(lo + off) = bf4{l4[0], l4[1], l4[2], l4[3]};
}

// ---------------- transpose + split: in[Kd, segN] -> out[rowBase+n][Kd] --------
__device__ __forceinline__ void trans_split_body(const float* __restrict__ ib,
                                                 bf16* __restrict__ oh,
                                                 bf16* __restrict__ ol,
                                                 int Kd, int segN,
                                                 int k0, int n0, size_t rowBase,
                                                 int tx, int ty, float s[32][33])
{
    #pragma unroll
    for (int ii = 0; ii < 4; ii++)
        s[ty + ii * 8][tx] = ib[(size_t)(k0 + ty + ii * 8) * segN + n0 + tx];
    __syncthreads();
    #pragma unroll
    for (int ii = 0; ii < 4; ii++) {
        int n = n0 + ty + ii * 8;
        float v = s[tx][ty + ii * 8];
        bf16 h = __float2bfloat16_rn(v);
        bf16 l = __float2bfloat16_rn(v - __bfloat162float(h));
        size_t o = (rowBase + n) * (size_t)Kd + k0 + tx;
        oh[o] = h; ol[o] = l;
    }
}

// fully fused weight prep:
//   z in [0,48): QKV seg = z>>4, head = z&15 (Kd=1024, segN=64)
//   z == 48:     W1 (Kd=1024, segN=4096)
//   z == 49:     W2 (Kd=4096, segN=1024)
// grid: x = 4096/32 = 128 (max Kd tiles), y = 4096/32 = 128 (max segN tiles), z = 50
// guards skip out-of-range tiles for the smaller segments.
__global__ void __launch_bounds__(256) trans_split_all(
    const float* __restrict__ Wq, const float* __restrict__ Wk,
    const float* __restrict__ Wv, const float* __restrict__ W1,
    const float* __restrict__ W2,
    bf16* __restrict__ qkvh, bf16* __restrict__ qkvl,
    bf16* __restrict__ w1h,  bf16* __restrict__ w1l,
    bf16* __restrict__ w2h,  bf16* __restrict__ w2l)
{
    __shared__ float s[32][33];
    int k0 = blockIdx.x * 32, n0 = blockIdx.y * 32, z = blockIdx.z;
    int tx = threadIdx.x & 31, ty = threadIdx.x >> 5;

    if (z < 48) {
        if (k0 >= Dsz || n0 >= DHsz) return;
        int seg = z >> 4, head = z & 15;
        const float* W = (seg == 0) ? Wq : (seg == 1) ? Wk : Wv;
        trans_split_body(W + (size_t)head * Dsz * DHsz,
                         qkvh + (size_t)seg * Dsz * Dsz,
                         qkvl + (size_t)seg * Dsz * Dsz,
                         Dsz, DHsz, k0, n0, (size_t)head * DHsz, tx, ty, s);
    } else if (z == 48) {
        if (k0 >= Dsz) return;   // n0 < 4096 always
        trans_split_body(W1, w1h, w1l, Dsz, FFsz, k0, n0, 0, tx, ty, s);
    } else {
        if (n0 >= Dsz) return;   // k0 < 4096 always
        trans_split_body(W2, w2h, w2l, FFsz, Dsz, k0, n0, 0, tx, ty, s);
    }
}

// ---------------- mma.sync GEMM, bf16-split 3-pass (round-7 proven config) -----
// 128x128 CTA tile, 8 warps (4m x 2n), warp tile 32x64, K-slab 32, 2-stage.
// __launch_bounds__(256,2) forces <=128 regs -> guaranteed 2 CTAs/SM.
#define MATB   10240
#define STAGEB (4*MATB)
#define GSMEM  (2*STAGEB)   // 81920

template<int MODE>
__global__ void __launch_bounds__(256, 2) gemm_mma(
    const bf16* __restrict__ Ahi, const bf16* __restrict__ Alo,
    const bf16* __restrict__ Bhi, const bf16* __restrict__ Blo,
    const float* __restrict__ bias,          // MODE 1/2; MODE 0: q bias
    const float* __restrict__ biasK,         // MODE 0 only
    const float* __restrict__ biasV,         // MODE 0 only
    float* __restrict__ O0,
    bf16* __restrict__ OH, bf16* __restrict__ OL,
    bf16* __restrict__ Qh, bf16* __restrict__ Ql,
    bf16* __restrict__ Kh, bf16* __restrict__ Kl,
    bf16* __restrict__ Vh, bf16* __restrict__ Vl,
    int N, int K)
{
    extern __shared__ __align__(1024) char smem[];
    uint32_t sb = smem_u32(smem);
    int tid = threadIdx.x, wid = tid >> 5, lane = tid & 31;
    int m0 = blockIdx.y * 128, n0 = blockIdx.x * 128;
    int wm = (wid & 3) * 32, wn = (wid >> 2) * 64;

    const char* gbase[4] = {
        (const char*)(Ahi + (size_t)m0 * K),
        (const char*)(Alo + (size_t)m0 * K),
        (const char*)(Bhi + (size_t)n0 * K),
        (const char*)(Blo + (size_t)n0 * K)};
    const size_t ldb = (size_t)K * 2;

    const int lrow = tid >> 1;           // 0..127
    const int lcc  = (tid & 1) * 32;     // byte col within 64B slab row

    float acc[2][8][4];
    #pragma unroll
    for (int t = 0; t < 2; t++)
        #pragma unroll
        for (int j = 0; j < 8; j++)
            #pragma unroll
            for (int q = 0; q < 4; q++) acc[t][j][q] = 0.f;

    int nslab = K >> 5;

    // ---- prologue: load stage 0
    {
        uint32_t stg = sb;
        #pragma unroll
        for (int mat = 0; mat < 4; mat++) {
            const char* g = gbase[mat] + (size_t)lrow * ldb + lcc;
            uint32_t dst = stg + mat * MATB + lrow * 80 + lcc;
            cp16(dst, g); cp16(dst + 16, g + 16);
        }
        cp_commit();
    }

    const int arow = lane & 15;
    const int akh  = (lane >> 4) * 16;
    const int bn   = ((lane >> 4) & 1) * 8 + (lane & 7);
    const int bkh  = ((lane >> 3) & 1) * 16;

    for (int s = 0; s < nslab; ++s) {
        uint32_t stg = sb + (s & 1) * STAGEB;
        if (s + 1 < nslab) {
            uint32_t nstg = sb + ((s + 1) & 1) * STAGEB;
            #pragma unroll
            for (int mat = 0; mat < 4; mat++) {
                const char* g = gbase[mat] + (size_t)lrow * ldb + (size_t)(s + 1) * 64 + lcc;
                uint32_t dst = nstg + mat * MATB + lrow * 80 + lcc;
                cp16(dst, g); cp16(dst + 16, g + 16);
            }
            cp_commit();
            cp_wait1();
        } else {
            cp_wait0();
        }
        __syncthreads();

        #pragma unroll
        for (int ks = 0; ks < 2; ks++) {
            int kb = ks * 32;
            uint32_t ah[8], al[8];
            #pragma unroll
            for (int t = 0; t < 2; t++) {
                uint32_t ra = stg + (wm + t * 16 + arow) * 80 + kb + akh;
                ldsm4(&ah[t * 4], ra);
                ldsm4(&al[t * 4], ra + MATB);
            }
            #pragma unroll
            for (int p = 0; p < 4; p++) {
                uint32_t rb = stg + 2 * MATB + (wn + p * 16 + bn) * 80 + kb + bkh;
                uint32_t bh[4], bl[4];
                ldsm4(bh, rb);
                ldsm4(bl, rb + MATB);
                #pragma unroll
                for (int t = 0; t < 2; t++) {
                    mma_bf16(acc[t][p*2+0], &ah[t*4], &bh[0]);
                    mma_bf16(acc[t][p*2+1], &ah[t*4], &bh[2]);
                    mma_bf16(acc[t][p*2+0], &ah[t*4], &bl[0]);
                    mma_bf16(acc[t][p*2+1], &ah[t*4], &bl[2]);
                    mma_bf16(acc[t][p*2+0], &al[t*4], &bh[0]);
                    mma_bf16(acc[t][p*2+1], &al[t*4], &bh[2]);
                }
            }
        }
        __syncthreads();
    }

    // ---- epilogue: direct fragment stores
    int g2 = lane >> 2, c2 = (lane & 3) * 2;
    #pragma unroll
    for (int t = 0; t < 2; t++) {
        #pragma unroll
        for (int j = 0; j < 8; j++) {
            int m = m0 + wm + t * 16 + g2;
            int n = n0 + wn + j * 8 + c2;
            float b0, b1;
            if (MODE == 0) {
                const float* bsel = (n < 1024) ? bias : (n < 2048) ? biasK : biasV;
                b0 = bsel[n & 1023]; b1 = bsel[(n & 1023) + 1];
            } else {
                b0 = bias[n]; b1 = bias[n + 1];
            }
            float v00 = acc[t][j][0] + b0, v01 = acc[t][j][1] + b1;
            float v10 = acc[t][j][2] + b0, v11 = acc[t][j][3] + b1;
            if (MODE == 0) {
                int which = n >> 10, hh = (n >> 6) & 15, e = n & 63;
                int b_ = m >> 11, s0 = m & 2047;
                bf16 h00 = __float2bfloat16_rn(v00), h01 = __float2bfloat16_rn(v01);
                bf16 h10 = __float2bfloat16_rn(v10), h11 = __float2bfloat16_rn(v11);
                bf16 l00 = __float2bfloat16_rn(v00 - __bfloat162float(h00));
                bf16 l01 = __float2bfloat16_rn(v01 - __bfloat162float(h01));
                bf16 l10 = __float2bfloat16_rn(v10 - __bfloat162float(h10));
                bf16 l11 = __float2bfloat16_rn(v11 - __bfloat162float(h11));
                if (which < 2) {
                    bf16* dh_ = (which == 0) ? Qh : Kh;
                    bf16* dl_ = (which == 0) ? Ql : Kl;
                    size_t base = ((size_t)(b_ * Hsz + hh) * Ssz + s0) * 64 + e;
                    *(bf2*)&dh_[base] = bf2{h00, h01};
                    *(bf2*)&dl_[base] = bf2{l00, l01};
                    *(bf2*)&dh_[base + 8 * 64] = bf2{h10, h11};
                    *(bf2*)&dl_[base + 8 * 64] = bf2{l10, l11};
                } else {
                    size_t base = ((size_t)(b_ * Hsz + hh) * 64 + e) * Ssz + s0;
                    Vh[base]            = h00;  Vl[base]            = l00;
                    Vh[base + Ssz]      = h01;  Vl[base + Ssz]      = l01;
                    Vh[base + 8]        = h10;  Vl[base + 8]        = l10;
                    Vh[base + Ssz + 8]  = h11;  Vl[base + Ssz + 8]  = l11;
                }
            } else if (MODE == 1) {
                v00 = gelu_exact(v00); v01 = gelu_exact(v01);
                v10 = gelu_exact(v10); v11 = gelu_exact(v11);
                bf16 h00 = __float2bfloat16_rn(v00), h01 = __float2bfloat16_rn(v01);
                bf16 h10 = __float2bfloat16_rn(v10), h11 = __float2bfloat16_rn(v11);
                bf16 l00 = __float2bfloat16_rn(v00 - __bfloat162float(h00));
                bf16 l01 = __float2bfloat16_rn(v01 - __bfloat162float(h01));
                bf16 l10 = __float2bfloat16_rn(v10 - __bfloat162float(h10));
                bf16 l11 = __float2bfloat16_rn(v11 - __bfloat162float(h11));
                size_t r0 = (size_t)m * N + n, r1 = (size_t)(m + 8) * N + n;
                *(bf2*)&OH[r0] = bf2{h00, h01};
                *(bf2*)&OH[r1] = bf2{h10, h11};
                *(bf2*)&OL[r0] = bf2{l00, l01};
                *(bf2*)&OL[r1] = bf2{l10, l11};
            } else {
                size_t r0 = (size_t)m * N + n, r1 = (size_t)(m + 8) * N + n;
                float2 c0 = *(float2*)&O0[r0];
                float2 c1 = *(float2*)&O0[r1];
                *(float2*)&O0[r0] = make_float2(v00 + c0.x, v01 + c0.y);
                *(float2*)&O0[r1] = make_float2(v10 + c1.x, v11 + c1.y);
            }
        }
    }
}

// ---------------- tensor-core flash attention (causal) — round-13 best ---------
#define AMAT 9216
#define ASMEM (6*AMAT)   // Qh Ql Kh Kl Vth Vtl = 55296

__global__ void __launch_bounds__(128, 3) attn_mma(
    const bf16* __restrict__ qh, const bf16* __restrict__ ql,
    const bf16* __restrict__ kh, const bf16* __restrict__ kl,
    const bf16* __restrict__ vth, const bf16* __restrict__ vtl,
    const float* __restrict__ x, float* __restrict__ out)
{
    extern __shared__ __align__(1024) char asmem[];
    uint32_t sb = smem_u32(asmem);
    const uint32_t sQh = sb, sKh = sb + 2*AMAT, sVh = sb + 4*AMAT;

    int tid = threadIdx.x, lane = tid & 31, wid = tid >> 5;
    int bh = blockIdx.y;
    int qt = gridDim.x - 1 - blockIdx.x;
    int q0 = qt * 64;
    int wm = wid * 16;

    const bf16* qhg = qh + ((size_t)bh * Ssz + q0) * 64;
    const bf16* qlg = ql + ((size_t)bh * Ssz + q0) * 64;
    const bf16* khg = kh + (size_t)bh * Ssz * 64;
    const bf16* klg = kl + (size_t)bh * Ssz * 64;
    const bf16* vthg = vth + (size_t)bh * 64 * Ssz;
    const bf16* vtlg = vtl + (size_t)bh * 64 * Ssz;

    #pragma unroll
    for (int i = 0; i < 4; i++) {
        int ch = i * 128 + tid;
        int r = ch >> 3, c = (ch & 7) * 16;
        cp16(sQh + r * 144 + c, (const char*)qhg + r * 128 + c);
        cp16(sQh + AMAT + r * 144 + c, (const char*)qlg + r * 128 + c);
    }
    cp_commit(); cp_wait0(); __syncthreads();

    const int arow = lane & 15;
    const int akh  = (lane >> 4) * 16;
    const int bn   = ((lane >> 4) & 1) * 8 + (lane & 7);
    const int bkh  = ((lane >> 3) & 1) * 16;

    uint32_t qfh[4][4], qfl[4][4];
    #pragma unroll
    for (int kc = 0; kc < 4; kc++) {
        uint32_t a = sQh + (wm + arow) * 144 + kc * 32 + akh;
        ldsm4(qfh[kc], a);
        ldsm4(qfl[kc], a + AMAT);
    }

    float m0 = -1e30f, m1 = -1e30f, l0 = 0.f, l1 = 0.f;
    float o[4][2][4];
    #pragma unroll
    for (int pd = 0; pd < 4; pd++)
        #pragma unroll
        for (int f = 0; f < 2; f++)
            #pragma unroll
            for (int e = 0; e < 4; e++) o[pd][f][e] = 0.f;

    int r0g = q0 + wm + (lane >> 2);
    int ntiles = qt + 1;

    for (int t = 0; t < ntiles; t++) {
        int j0 = t * 64;
        __syncthreads();
        #pragma unroll
        for (int i = 0; i < 4; i++) {
            int ch = i * 128 + tid;
            int r = ch >> 3, c = (ch & 7) * 16;
            cp16(sKh + r * 144 + c,        (const char*)(khg + (size_t)(j0 + r) * 64) + c);
            cp16(sKh + AMAT + r * 144 + c, (const char*)(klg + (size_t)(j0 + r) * 64) + c);
            cp16(sVh + r * 144 + c,        (const char*)(vthg + (size_t)r * Ssz + j0) + c);
            cp16(sVh + AMAT + r * 144 + c, (const char*)(vtlg + (size_t)r * Ssz + j0) + c);
        }
        cp_commit(); cp_wait0(); __syncthreads();

        float s[4][2][4];
        #pragma unroll
        for (int p = 0; p < 4; p++)
            #pragma unroll
            for (int f = 0; f < 2; f++)
                #pragma unroll
                for (int e = 0; e < 4; e++) s[p][f][e] = 0.f;

        #pragma unroll
        for (int kc = 0; kc < 4; kc++) {
            #pragma unroll
            for (int p = 0; p < 4; p++) {
                uint32_t kf[4], kg[4];
                uint32_t a = sKh + (p * 16 + bn) * 144 + kc * 32 + bkh;
                ldsm4(kf, a);
                ldsm4(kg, a + AMAT);
                mma_bf16(s[p][0], qfh[kc], &kf[0]);
                mma_bf16(s[p][1], qfh[kc], &kf[2]);
                mma_bf16(s[p][0], qfh[kc], &kg[0]);
                mma_bf16(s[p][1], qfh[kc], &kg[2]);
                mma_bf16(s[p][0], qfl[kc], &kf[0]);
                mma_bf16(s[p][1], qfl[kc], &kf[2]);
            }
        }

        bool diag = (j0 == q0);
        #pragma unroll
        for (int p = 0; p < 4; p++)
            #pragma unroll
            for (int f = 0; f < 2; f++) {
                int colb = j0 + p * 16 + f * 8 + (lane & 3) * 2;
                #pragma unroll
                for (int e = 0; e < 4; e++) {
                    float sv = s[p][f][e] * 0.125f;
                    if (diag) {
                        int col = colb + (e & 1);
                        int row = r0g + ((e >> 1) << 3);
                        if (col > row) sv = -1e30f;
                    }
                    s[p][f][e] = sv;
                }
            }

        float rx0 = -1e30f, rx1 = -1e30f;
        #pragma unroll
        for (int p = 0; p < 4; p++)
            #pragma unroll
            for (int f = 0; f < 2; f++) {
                rx0 = fmaxf(rx0, fmaxf(s[p][f][0], s[p][f][1]));
                rx1 = fmaxf(rx1, fmaxf(s[p][f][2], s[p][f][3]));
            }
        rx0 = fmaxf(rx0, __shfl_xor_sync(0xffffffffu, rx0, 1));
        rx0 = fmaxf(rx0, __shfl_xor_sync(0xffffffffu, rx0, 2));
        rx1 = fmaxf(rx1, __shfl_xor_sync(0xffffffffu, rx1, 1));
        rx1 = fmaxf(rx1, __shfl_xor_sync(0xffffffffu, rx1, 2));
        float mn0 = fmaxf(m0, rx0), mn1 = fmaxf(m1, rx1);
        float a0 = __expf(m0 - mn0), a1 = __expf(m1 - mn1);
        m0 = mn0; m1 = mn1;

        float sum0 = 0.f, sum1 = 0.f;
        #pragma unroll
        for (int p = 0; p < 4; p++)
            #pragma unroll
            for (int f = 0; f < 2; f++) {
                float p0 = __expf(s[p][f][0] - mn0);
                float p1 = __expf(s[p][f][1] - mn0);
                float p2 = __expf(s[p][f][2] - mn1);
                float p3 = __expf(s[p][f][3] - mn1);
                s[p][f][0] = p0; s[p][f][1] = p1; s[p][f][2] = p2; s[p][f][3] = p3;
                sum0 += p0 + p1; sum1 += p2 + p3;
            }
        sum0 += __shfl_xor_sync(0xffffffffu, sum0, 1);
        sum0 += __shfl_xor_sync(0xffffffffu, sum0, 2);
        sum1 += __shfl_xor_sync(0xffffffffu, sum1, 1);
        sum1 += __shfl_xor_sync(0xffffffffu, sum1, 2);
        l0 = l0 * a0 + sum0;
        l1 = l1 * a1 + sum1;
        #pragma unroll
        for (int pd = 0; pd < 4; pd++)
            #pragma unroll
            for (int f = 0; f < 2; f++) {
                o[pd][f][0] *= a0; o[pd][f][1] *= a0;
                o[pd][f][2] *= a1; o[pd][f][3] *= a1;
            }

        #pragma unroll
        for (int kc = 0; kc < 4; kc++) {
            uint32_t pah[4], pal[4];
            #pragma unroll
            for (int f = 0; f < 2; f++) {
                float x0 = s[kc][f][0], x1 = s[kc][f][1];
                float x2 = s[kc][f][2], x3 = s[kc][f][3];
                uint32_t h01 = packbf2(x0, x1);
                uint32_t h23 = packbf2(x2, x3);
                __nv_bfloat162 hb01 = *(__nv_bfloat162*)&h01;
                __nv_bfloat162 hb23 = *(__nv_bfloat162*)&h23;
                uint32_t lo01 = packbf2(x0 - __bfloat162float(hb01.x),
                                        x1 - __bfloat162float(hb01.y));
                uint32_t lo23 = packbf2(x2 - __bfloat162float(hb23.x),
                                        x3 - __bfloat162float(hb23.y));
                pah[f * 2 + 0] = h01;  pal[f * 2 + 0] = lo01;
                pah[f * 2 + 1] = h23;  pal[f * 2 + 1] = lo23;
            }
            #pragma unroll
            for (int pd = 0; pd < 4; pd++) {
                uint32_t vf[4], vg[4];
                uint32_t a = sVh + (pd * 16 + bn) * 144 + kc * 32 + bkh;
                ldsm4(vf, a);
                ldsm4(vg, a + AMAT);
                mma_bf16(o[pd][0], pah, &vf[0]);
                mma_bf16(o[pd][1], pah, &vf[2]);
                mma_bf16(o[pd][0], pah, &vg[0]);
                mma_bf16(o[pd][1], pah, &vg[2]);
                mma_bf16(o[pd][0], pal, &vf[0]);
                mma_bf16(o[pd][1], pal, &vf[2]);
            }
        }
    }

    float inv0 = 1.0f / l0, inv1 = 1.0f / l1;
    int b_ = bh >> 4, hh = bh & 15;
    #pragma unroll
    for (int pd = 0; pd < 4; pd++)
        #pragma unroll
        for (int f = 0; f < 2; f++) {
            int dh = pd * 16 + f * 8 + (lane & 3) * 2;
            size_t i0 = ((size_t)(b_ * Ssz + r0g)) * Dsz + hh * 64 + dh;
            size_t i1 = i0 + (size_t)8 * Dsz;
            float2 x0 = *(const float2*)&x[i0];
            float2 x1 = *(const float2*)&x[i1];
            *(float2*)&out[i0] = make_float2(x0.x + o[pd][f][0] * inv0,
                                             x0.y + o[pd][f][1] * inv0);
            *(float2*)&out[i1] = make_float2(x1.x + o[pd][f][2] * inv1,
                                             x1.y + o[pd][f][3] * inv1);
        }
}

// ---------------- launch --------------------------------------------------------
extern "C" void kernel_launch(void* const* d_in, const int* in_sizes, int n_in,
                              void* d_out, int out_size)
{
    const float* x    = (const float*)d_in[0];
    const float* Wq   = (const float*)d_in[1];
    const float* bq   = (const float*)d_in[2];
    const float* Wk   = (const float*)d_in[3];
    const float* bk   = (const float*)d_in[4];
    const float* Wv   = (const float*)d_in[5];
    const float* bv   = (const float*)d_in[6];
    const float* ln1g = (const float*)d_in[7];
    const float* ln1b = (const float*)d_in[8];
    const float* ln2g = (const float*)d_in[9];
    const float* ln2b = (const float*)d_in[10];
    const float* W1   = (const float*)d_in[11];
    const float* b1   = (const float*)d_in[12];
    const float* W2   = (const float*)d_in[13];
    const float* b2   = (const float*)d_in[14];
    float* out = (float*)d_out;

    bf16 *hhi, *hlo, *midhi, *midlo, *wqkvh, *wqkvl, *w1h, *w1l, *w2h, *w2l;
    bf16 *qh_, *ql_, *kh_, *kl_, *vth_, *vtl_;
    cudaGetSymbolAddress((void**)&hhi,   g_hhi);
    cudaGetSymbolAddress((void**)&hlo,   g_hlo);
    cudaGetSymbolAddress((void**)&midhi, g_midhi);
    cudaGetSymbolAddress((void**)&midlo, g_midlo);
    cudaGetSymbolAddress((void**)&wqkvh, g_wqkvT_hi);
    cudaGetSymbolAddress((void**)&wqkvl, g_wqkvT_lo);
    cudaGetSymbolAddress((void**)&w1h,   g_w1T_hi);
    cudaGetSymbolAddress((void**)&w1l,   g_w1T_lo);
    cudaGetSymbolAddress((void**)&w2h,   g_w2T_hi);
    cudaGetSymbolAddress((void**)&w2l,   g_w2T_lo);
    cudaGetSymbolAddress((void**)&qh_,   g_qh);
    cudaGetSymbolAddress((void**)&ql_,   g_ql);
    cudaGetSymbolAddress((void**)&kh_,   g_kh);
    cudaGetSymbolAddress((void**)&kl_,   g_kl);
    cudaGetSymbolAddress((void**)&vth_,  g_vth);
    cudaGetSymbolAddress((void**)&vtl_,  g_vtl);

    cudaFuncSetAttribute(gemm_mma<0>, cudaFuncAttributeMaxDynamicSharedMemorySize, GSMEM);
    cudaFuncSetAttribute(gemm_mma<1>, cudaFuncAttributeMaxDynamicSharedMemorySize, GSMEM);
    cudaFuncSetAttribute(gemm_mma<2>, cudaFuncAttributeMaxDynamicSharedMemorySize, GSMEM);
    cudaFuncSetAttribute(attn_mma, cudaFuncAttributeMaxDynamicSharedMemorySize, ASMEM);

    // weight prep (single fused launch: QKV heads + W1 + W2)
    trans_split_all<<<dim3(FFsz/32, FFsz/32, 50), 256>>>(
        Wq, Wk, Wv, W1, W2, wqkvh, wqkvl, w1h, w1l, w2h, w2l);

    // 1) LN1 -> bf16 split
    ln_split<<<Mrows, 256>>>(x, ln1g, ln1b, hhi, hlo);

    // 2) fused QKV GEMM (N = 3072) -> bf16 q/k + transposed v (bias selected inline)
    gemm_mma<0><<<dim3(3*Dsz/128, Mrows/128), 256, GSMEM>>>(
        hhi, hlo, wqkvh, wqkvl, bq, bk, bv, nullptr, nullptr, nullptr,
        qh_, ql_, kh_, kl_, vth_, vtl_, 3*Dsz, Dsz);

    // 3) tensor-core attention + residual -> out = x1
    attn_mma<<<dim3(Ssz/64, BH), 128, ASMEM>>>(qh_, ql_, kh_, kl_, vth_, vtl_, x, out);

    // 4) LN2 -> bf16 split
    ln_split<<<Mrows, 256>>>(out, ln2g, ln2b, hhi, hlo);

    // 5) mid = GELU(h @ W1 + b1), split to bf16
    gemm_mma<1><<<dim3(FFsz/128, Mrows/128), 256, GSMEM>>>(
        hhi, hlo, w1h, w1l, b1, nullptr, nullptr, nullptr, midhi, midlo,
        nullptr, nullptr, nullptr, nullptr, nullptr, nullptr, FFsz, Dsz);

    // 6) out = x1 + mid @ W2 + b2
    gemm_mma<2><<<dim3(Dsz/128, Mrows/128), 256, GSMEM>>>(
        midhi, midlo, w2h, w2l, b2, nullptr, nullptr, out, nullptr, nullptr,
        nullptr, nullptr, nullptr, nullptr, nullptr, nullptr, Dsz, FFsz);
}

// round 15
// speedup vs baseline: 1.3283x; 1.3283x over previous
#include <cuda_runtime.h>
#include <cuda_bf16.h>
#include <math.h>
#include <stdint.h>

#define Bsz 2
#define Ssz 2048
#define Dsz 1024
#define Hsz 16
#define DHsz 64
#define FFsz 4096
#define Mrows (Bsz*Ssz)   // 4096
#define BH    (Bsz*Hsz)   // 32

typedef __nv_bfloat16 bf16;

// ---------------- scratch (device globals) ----------------------------------
__device__ bf16  g_hhi[Mrows * Dsz];
__device__ bf16  g_hlo[Mrows * Dsz];
__device__ bf16  g_midhi[(size_t)Mrows * FFsz];
__device__ bf16  g_midlo[(size_t)Mrows * FFsz];
__device__ bf16  g_wqkvT_hi[3 * Dsz * Dsz];
__device__ bf16  g_wqkvT_lo[3 * Dsz * Dsz];
__device__ bf16  g_w1T_hi[FFsz * Dsz];
__device__ bf16  g_w1T_lo[FFsz * Dsz];
__device__ bf16  g_w2T_hi[Dsz * FFsz];
__device__ bf16  g_w2T_lo[Dsz * FFsz];
__device__ bf16  g_qh[BH * Ssz * DHsz];
__device__ bf16  g_ql[BH * Ssz * DHsz];
__device__ bf16  g_kh[BH * Ssz * DHsz];
__device__ bf16  g_kl[BH * Ssz * DHsz];
__device__ bf16  g_vth[BH * DHsz * Ssz];   // transposed: [bh][dh][s]
__device__ bf16  g_vtl[BH * DHsz * Ssz];

// ---------------- PTX helpers -------------------------------------------------
__device__ __forceinline__ uint32_t smem_u32(const void* p) {
    uint32_t a;
    asm("{ .reg .u64 t; cvta.to.shared.u64 t, %1; cvt.u32.u64 %0, t; }" : "=r"(a) : "l"(p));
    return a;
}
__device__ __forceinline__ void cp16(uint32_t dst, const void* src) {
    asm volatile("cp.async.cg.shared.global [%0], [%1], 16;" :: "r"(dst), "l"(src));
}
__device__ __forceinline__ void cp_commit() { asm volatile("cp.async.commit_group;"); }
__device__ __forceinline__ void cp_wait1()  { asm volatile("cp.async.wait_group 1;" ::: "memory"); }
__device__ __forceinline__ void cp_wait0()  { asm volatile("cp.async.wait_group 0;" ::: "memory"); }

__device__ __forceinline__ void ldsm4(uint32_t* r, uint32_t addr) {
    asm volatile("ldmatrix.sync.aligned.m8n8.x4.shared.b16 {%0,%1,%2,%3}, [%4];"
        : "=r"(r[0]), "=r"(r[1]), "=r"(r[2]), "=r"(r[3]) : "r"(addr));
}
// Non-volatile — pure register op; lets ptxas interleave MMAs with ldsm.
__device__ __forceinline__ void mma_bf16(float* d, const uint32_t* a, const uint32_t* b) {
    asm("mma.sync.aligned.m16n8k16.row.col.f32.bf16.bf16.f32 "
        "{%0,%1,%2,%3}, {%4,%5,%6,%7}, {%8,%9}, {%0,%1,%2,%3};"
        : "+f"(d[0]), "+f"(d[1]), "+f"(d[2]), "+f"(d[3])
        : "r"(a[0]), "r"(a[1]), "r"(a[2]), "r"(a[3]), "r"(b[0]), "r"(b[1]));
}

__device__ __forceinline__ float gelu_exact(float v) {
    return 0.5f * v * (1.0f + erff(v * 0.70710678118654752f));
}
struct __align__(8) bf4 { bf16 a, b, c, d; };
struct __align__(4) bf2 { bf16 a, b; };

__device__ __forceinline__ uint32_t packbf2(float a, float b) {
    __nv_bfloat162 t = __float22bfloat162_rn(make_float2(a, b));
    return *(uint32_t*)&t;
}

// ---------------- LayerNorm -> bf16 hi/lo split -------------------------------
__global__ void __launch_bounds__(256) ln_split(const float* __restrict__ x,
                                                const float* __restrict__ g,
                                                const float* __restrict__ beta,
                                                bf16* __restrict__ hi,
                                                bf16* __restrict__ lo)
{
    int row = blockIdx.x;
    int t   = threadIdx.x;
    float4 xv = ((const float4*)(x + (size_t)row * Dsz))[t];
    float s  = xv.x + xv.y + xv.z + xv.w;
    float ss = xv.x*xv.x + xv.y*xv.y + xv.z*xv.z + xv.w*xv.w;
    #pragma unroll
    for (int o = 16; o; o >>= 1) {
        s  += __shfl_xor_sync(0xffffffffu, s,  o);
        ss += __shfl_xor_sync(0xffffffffu, ss, o);
    }
    __shared__ float sh[16];
    int w = t >> 5;
    if ((t & 31) == 0) { sh[w] = s; sh[8 + w] = ss; }
    __syncthreads();
    s = 0.f; ss = 0.f;
    #pragma unroll
    for (int i = 0; i < 8; i++) { s += sh[i]; ss += sh[8 + i]; }
    float mu  = s * (1.0f / Dsz);
    float var = ss * (1.0f / Dsz) - mu * mu;
    float inv = rsqrtf(var + 1e-5f);
    float4 gv = ((const float4*)g)[t];
    float4 bv = ((const float4*)beta)[t];
    float r[4];
    r[0] = (xv.x - mu) * inv * gv.x + bv.x;
    r[1] = (xv.y - mu) * inv * gv.y + bv.y;
    r[2] = (xv.z - mu) * inv * gv.z + bv.z;
    r[3] = (xv.w - mu) * inv * gv.w + bv.w;
    bf16 h4[4], l4[4];
    #pragma unroll
    for (int i = 0; i < 4; i++) {
        h4[i] = __float2bfloat16_rn(r[i]);
        l4[i] = __float2bfloat16_rn(r[i] - __bfloat162float(h4[i]));
    }
    size_t off = (size_t)row * Dsz + t * 4;
    *(bf4*)(hi + off) = bf4{h4[0], h4[1], h4[2], h4[3]};
    *(bf4*)(lo + off) = bf4{l4[0], l4[1], l4[2], l4[3]};
}

// ---------------- transpose + split: in[Kd, segN] -> out[rowBase+n][Kd] --------
__device__ __forceinline__ void trans_split_body(const float* __restrict__ ib,
                                                 bf16* __restrict__ oh,
                                                 bf16* __restrict__ ol,
                                                 int Kd, int segN,
                                                 int k0, int n0, size_t rowBase,
                                                 int tx, int ty, float s[32][33])
{
    #pragma unroll
    for (int ii = 0; ii < 4; ii++)
        s[ty + ii * 8][tx] = ib[(size_t)(k0 + ty + ii * 8) * segN + n0 + tx];
    __syncthreads();
    #pragma unroll
    for (int ii = 0; ii < 4; ii++) {
        int n = n0 + ty + ii * 8;
        float v = s[tx][ty + ii * 8];
        bf16 h = __float2bfloat16_rn(v);
        bf16 l = __float2bfloat16_rn(v - __bfloat162float(h));
        size_t o = (rowBase + n) * (size_t)Kd + k0 + tx;
        oh[o] = h; ol[o] = l;
    }
}

__global__ void __launch_bounds__(256) trans_split(const float* __restrict__ in,
                                                   bf16* __restrict__ oh,
                                                   bf16* __restrict__ ol,
                                                   int Kd, int segN)
{
    __shared__ float s[32][33];
    int k0 = blockIdx.x * 32, n0 = blockIdx.y * 32, z = blockIdx.z;
    trans_split_body(in + (size_t)z * Kd * segN, oh, ol, Kd, segN,
                     k0, n0, (size_t)z * segN,
                     threadIdx.x & 31, threadIdx.x >> 5, s);
}

// fused QKV weight prep: z in [0,48): seg = z>>4 (q/k/v), head = z&15
__global__ void __launch_bounds__(256) trans_split_qkv(const float* __restrict__ Wq,
                                                       const float* __restrict__ Wk,
                                                       const float* __restrict__ Wv,
                                                       bf16* __restrict__ oh,
                                                       bf16* __restrict__ ol)
{
    __shared__ float s[32][33];
    int k0 = blockIdx.x * 32, n0 = blockIdx.y * 32, z = blockIdx.z;
    int seg = z >> 4, head = z & 15;
    const float* W = (seg == 0) ? Wq : (seg == 1) ? Wk : Wv;
    trans_split_body(W + (size_t)head * Dsz * DHsz,
                     oh + (size_t)seg * Dsz * Dsz, ol + (size_t)seg * Dsz * Dsz,
                     Dsz, DHsz, k0, n0, (size_t)head * DHsz,
                     threadIdx.x & 31, threadIdx.x >> 5, s);
}

// ---------------- mma.sync GEMM, bf16-split 3-pass (round-7 proven config) -----
// 128x128 CTA tile, 8 warps (4m x 2n), warp tile 32x64, K-slab 32, 2-stage.
// __launch_bounds__(256,2) forces <=128 regs -> guaranteed 2 CTAs/SM.
#define MATB   10240
#define STAGEB (4*MATB)
#define GSMEM  (2*STAGEB)   // 81920

template<int MODE>
__global__ void __launch_bounds__(256, 2) gemm_mma(
    const bf16* __restrict__ Ahi, const bf16* __restrict__ Alo,
    const bf16* __restrict__ Bhi, const bf16* __restrict__ Blo,
    const float* __restrict__ bias,          // MODE 1/2; MODE 0: q bias
    const float* __restrict__ biasK,         // MODE 0 only
    const float* __restrict__ biasV,         // MODE 0 only
    float* __restrict__ O0,
    bf16* __restrict__ OH, bf16* __restrict__ OL,
    bf16* __restrict__ Qh, bf16* __restrict__ Ql,
    bf16* __restrict__ Kh, bf16* __restrict__ Kl,
    bf16* __restrict__ Vh, bf16* __restrict__ Vl,
    int N, int K)
{
    extern __shared__ __align__(1024) char smem[];
    uint32_t sb = smem_u32(smem);
    int tid = threadIdx.x, wid = tid >> 5, lane = tid & 31;
    int m0 = blockIdx.y * 128, n0 = blockIdx.x * 128;
    int wm = (wid & 3) * 32, wn = (wid >> 2) * 64;

    const char* gbase[4] = {
        (const char*)(Ahi + (size_t)m0 * K),
        (const char*)(Alo + (size_t)m0 * K),
        (const char*)(Bhi + (size_t)n0 * K),
        (const char*)(Blo + (size_t)n0 * K)};
    const size_t ldb = (size_t)K * 2;

    const int lrow = tid >> 1;           // 0..127
    const int lcc  = (tid & 1) * 32;     // byte col within 64B slab row

    float acc[2][8][4];
    #pragma unroll
    for (int t = 0; t < 2; t++)
        #pragma unroll
        for (int j = 0; j < 8; j++)
            #pragma unroll
            for (int q = 0; q < 4; q++) acc[t][j][q] = 0.f;

    int nslab = K >> 5;

    // ---- prologue: load stage 0
    {
        uint32_t stg = sb;
        #pragma unroll
        for (int mat = 0; mat < 4; mat++) {
            const char* g = gbase[mat] + (size_t)lrow * ldb + lcc;
            uint32_t dst = stg + mat * MATB + lrow * 80 + lcc;
            cp16(dst, g); cp16(dst + 16, g + 16);
        }
        cp_commit();
    }

    const int arow = lane & 15;
    const int akh  = (lane >> 4) * 16;
    const int bn   = ((lane >> 4) & 1) * 8 + (lane & 7);
    const int bkh  = ((lane >> 3) & 1) * 16;

    for (int s = 0; s < nslab; ++s) {
        uint32_t stg = sb + (s & 1) * STAGEB;
        if (s + 1 < nslab) {
            uint32_t nstg = sb + ((s + 1) & 1) * STAGEB;
            #pragma unroll
            for (int mat = 0; mat < 4; mat++) {
                const char* g = gbase[mat] + (size_t)lrow * ldb + (size_t)(s + 1) * 64 + lcc;
                uint32_t dst = nstg + mat * MATB + lrow * 80 + lcc;
                cp16(dst, g); cp16(dst + 16, g + 16);
            }
            cp_commit();
            cp_wait1();
        } else {
            cp_wait0();
        }
        __syncthreads();

        #pragma unroll
        for (int ks = 0; ks < 2; ks++) {
            int kb = ks * 32;
            uint32_t ah[8], al[8];
            #pragma unroll
            for (int t = 0; t < 2; t++) {
                uint32_t ra = stg + (wm + t * 16 + arow) * 80 + kb + akh;
                ldsm4(&ah[t * 4], ra);
                ldsm4(&al[t * 4], ra + MATB);
            }
            #pragma unroll
            for (int p = 0; p < 4; p++) {
                uint32_t rb = stg + 2 * MATB + (wn + p * 16 + bn) * 80 + kb + bkh;
                uint32_t bh[4], bl[4];
                ldsm4(bh, rb);
                ldsm4(bl, rb + MATB);
                #pragma unroll
                for (int t = 0; t < 2; t++) {
                    mma_bf16(acc[t][p*2+0], &ah[t*4], &bh[0]);
                    mma_bf16(acc[t][p*2+1], &ah[t*4], &bh[2]);
                    mma_bf16(acc[t][p*2+0], &ah[t*4], &bl[0]);
                    mma_bf16(acc[t][p*2+1], &ah[t*4], &bl[2]);
                    mma_bf16(acc[t][p*2+0], &al[t*4], &bh[0]);
                    mma_bf16(acc[t][p*2+1], &al[t*4], &bh[2]);
                }
            }
        }
        __syncthreads();
    }

    // ---- epilogue: direct fragment stores
    int g2 = lane >> 2, c2 = (lane & 3) * 2;
    #pragma unroll
    for (int t = 0; t < 2; t++) {
        #pragma unroll
        for (int j = 0; j < 8; j++) {
            int m = m0 + wm + t * 16 + g2;
            int n = n0 + wn + j * 8 + c2;
            float b0, b1;
            if (MODE == 0) {
                const float* bsel = (n < 1024) ? bias : (n < 2048) ? biasK : biasV;
                b0 = bsel[n & 1023]; b1 = bsel[(n & 1023) + 1];
            } else {
                b0 = bias[n]; b1 = bias[n + 1];
            }
            float v00 = acc[t][j][0] + b0, v01 = acc[t][j][1] + b1;
            float v10 = acc[t][j][2] + b0, v11 = acc[t][j][3] + b1;
            if (MODE == 0) {
                int which = n >> 10, hh = (n >> 6) & 15, e = n & 63;
                int b_ = m >> 11, s0 = m & 2047;
                bf16 h00 = __float2bfloat16_rn(v00), h01 = __float2bfloat16_rn(v01);
                bf16 h10 = __float2bfloat16_rn(v10), h11 = __float2bfloat16_rn(v11);
                bf16 l00 = __float2bfloat16_rn(v00 - __bfloat162float(h00));
                bf16 l01 = __float2bfloat16_rn(v01 - __bfloat162float(h01));
                bf16 l10 = __float2bfloat16_rn(v10 - __bfloat162float(h10));
                bf16 l11 = __float2bfloat16_rn(v11 - __bfloat162float(h11));
                if (which < 2) {
                    bf16* dh_ = (which == 0) ? Qh : Kh;
                    bf16* dl_ = (which == 0) ? Ql : Kl;
                    size_t base = ((size_t)(b_ * Hsz + hh) * Ssz + s0) * 64 + e;
                    *(bf2*)&dh_[base] = bf2{h00, h01};
                    *(bf2*)&dl_[base] = bf2{l00, l01};
                    *(bf2*)&dh_[base + 8 * 64] = bf2{h10, h11};
                    *(bf2*)&dl_[base + 8 * 64] = bf2{l10, l11};
                } else {
                    size_t base = ((size_t)(b_ * Hsz + hh) * 64 + e) * Ssz + s0;
                    Vh[base]            = h00;  Vl[base]            = l00;
                    Vh[base + Ssz]      = h01;  Vl[base + Ssz]      = l01;
                    Vh[base + 8]        = h10;  Vl[base + 8]        = l10;
                    Vh[base + Ssz + 8]  = h11;  Vl[base + Ssz + 8]  = l11;
                }
            } else if (MODE == 1) {
                v00 = gelu_exact(v00); v01 = gelu_exact(v01);
                v10 = gelu_exact(v10); v11 = gelu_exact(v11);
                bf16 h00 = __float2bfloat16_rn(v00), h01 = __float2bfloat16_rn(v01);
                bf16 h10 = __float2bfloat16_rn(v10), h11 = __float2bfloat16_rn(v11);
                bf16 l00 = __float2bfloat16_rn(v00 - __bfloat162float(h00));
                bf16 l01 = __float2bfloat16_rn(v01 - __bfloat162float(h01));
                bf16 l10 = __float2bfloat16_rn(v10 - __bfloat162float(h10));
                bf16 l11 = __float2bfloat16_rn(v11 - __bfloat162float(h11));
                size_t r0 = (size_t)m * N + n, r1 = (size_t)(m + 8) * N + n;
                *(bf2*)&OH[r0] = bf2{h00, h01};
                *(bf2*)&OH[r1] = bf2{h10, h11};
                *(bf2*)&OL[r0] = bf2{l00, l01};
                *(bf2*)&OL[r1] = bf2{l10, l11};
            } else {
                size_t r0 = (size_t)m * N + n, r1 = (size_t)(m + 8) * N + n;
                float2 c0 = *(float2*)&O0[r0];
                float2 c1 = *(float2*)&O0[r1];
                *(float2*)&O0[r0] = make_float2(v00 + c0.x, v01 + c0.y);
                *(float2*)&O0[r1] = make_float2(v10 + c1.x, v11 + c1.y);
            }
        }
    }
}

// ---------------- tensor-core flash attention (causal) — round-13 best ---------
#define AMAT 9216
#define ASMEM (6*AMAT)   // Qh Ql Kh Kl Vth Vtl = 55296

__global__ void __launch_bounds__(128, 3) attn_mma(
    const bf16* __restrict__ qh, const bf16* __restrict__ ql,
    const bf16* __restrict__ kh, const bf16* __restrict__ kl,
    const bf16* __restrict__ vth, const bf16* __restrict__ vtl,
    const float* __restrict__ x, float* __restrict__ out)
{
    extern __shared__ __align__(1024) char asmem[];
    uint32_t sb = smem_u32(asmem);
    const uint32_t sQh = sb, sKh = sb + 2*AMAT, sVh = sb + 4*AMAT;

    int tid = threadIdx.x, lane = tid & 31, wid = tid >> 5;
    int bh = blockIdx.y;
    int qt = gridDim.x - 1 - blockIdx.x;
    int q0 = qt * 64;
    int wm = wid * 16;

    const bf16* qhg = qh + ((size_t)bh * Ssz + q0) * 64;
    const bf16* qlg = ql + ((size_t)bh * Ssz + q0) * 64;
    const bf16* khg = kh + (size_t)bh * Ssz * 64;
    const bf16* klg = kl + (size_t)bh * Ssz * 64;
    const bf16* vthg = vth + (size_t)bh * 64 * Ssz;
    const bf16* vtlg = vtl + (size_t)bh * 64 * Ssz;

    #pragma unroll
    for (int i = 0; i < 4; i++) {
        int ch = i * 128 + tid;
        int r = ch >> 3, c = (ch & 7) * 16;
        cp16(sQh + r * 144 + c, (const char*)qhg + r * 128 + c);
        cp16(sQh + AMAT + r * 144 + c, (const char*)qlg + r * 128 + c);
    }
    cp_commit(); cp_wait0(); __syncthreads();

    const int arow = lane & 15;
    const int akh  = (lane >> 4) * 16;
    const int bn   = ((lane >> 4) & 1) * 8 + (lane & 7);
    const int bkh  = ((lane >> 3) & 1) * 16;

    uint32_t qfh[4][4], qfl[4][4];
    #pragma unroll
    for (int kc = 0; kc < 4; kc++) {
        uint32_t a = sQh + (wm + arow) * 144 + kc * 32 + akh;
        ldsm4(qfh[kc], a);
        ldsm4(qfl[kc], a + AMAT);
    }

    float m0 = -1e30f, m1 = -1e30f, l0 = 0.f, l1 = 0.f;
    float o[4][2][4];
    #pragma unroll
    for (int pd = 0; pd < 4; pd++)
        #pragma unroll
        for (int f = 0; f < 2; f++)
            #pragma unroll
            for (int e = 0; e < 4; e++) o[pd][f][e] = 0.f;

    int r0g = q0 + wm + (lane >> 2);
    int ntiles = qt + 1;

    for (int t = 0; t < ntiles; t++) {
        int j0 = t * 64;
        __syncthreads();
        #pragma unroll
        for (int i = 0; i < 4; i++) {
            int ch = i * 128 + tid;
            int r = ch >> 3, c = (ch & 7) * 16;
            cp16(sKh + r * 144 + c,        (const char*)(khg + (size_t)(j0 + r) * 64) + c);
            cp16(sKh + AMAT + r * 144 + c, (const char*)(klg + (size_t)(j0 + r) * 64) + c);
            cp16(sVh + r * 144 + c,        (const char*)(vthg + (size_t)r * Ssz + j0) + c);
            cp16(sVh + AMAT + r * 144 + c, (const char*)(vtlg + (size_t)r * Ssz + j0) + c);
        }
        cp_commit(); cp_wait0(); __syncthreads();

        float s[4][2][4];
        #pragma unroll
        for (int p = 0; p < 4; p++)
            #pragma unroll
            for (int f = 0; f < 2; f++)
                #pragma unroll
                for (int e = 0; e < 4; e++) s[p][f][e] = 0.f;

        #pragma unroll
        for (int kc = 0; kc < 4; kc++) {
            #pragma unroll
            for (int p = 0; p < 4; p++) {
                uint32_t kf[4], kg[4];
                uint32_t a = sKh + (p * 16 + bn) * 144 + kc * 32 + bkh;
                ldsm4(kf, a);
                ldsm4(kg, a + AMAT);
                mma_bf16(s[p][0], qfh[kc], &kf[0]);
                mma_bf16(s[p][1], qfh[kc], &kf[2]);
                mma_bf16(s[p][0], qfh[kc], &kg[0]);
                mma_bf16(s[p][1], qfh[kc], &kg[2]);
                mma_bf16(s[p][0], qfl[kc], &kf[0]);
                mma_bf16(s[p][1], qfl[kc], &kf[2]);
            }
        }

        bool diag = (j0 == q0);
        #pragma unroll
        for (int p = 0; p < 4; p++)
            #pragma unroll
            for (int f = 0; f < 2; f++) {
                int colb = j0 + p * 16 + f * 8 + (lane & 3) * 2;
                #pragma unroll
                for (int e = 0; e < 4; e++) {
                    float sv = s[p][f][e] * 0.125f;
                    if (diag) {
                        int col = colb + (e & 1);
                        int row = r0g + ((e >> 1) << 3);
                        if (col > row) sv = -1e30f;
                    }
                    s[p][f][e] = sv;
                }
            }

        float rx0 = -1e30f, rx1 = -1e30f;
        #pragma unroll
        for (int p = 0; p < 4; p++)
            #pragma unroll
            for (int f = 0; f < 2; f++) {
                rx0 = fmaxf(rx0, fmaxf(s[p][f][0], s[p][f][1]));
                rx1 = fmaxf(rx1, fmaxf(s[p][f][2], s[p][f][3]));
            }
        rx0 = fmaxf(rx0, __shfl_xor_sync(0xffffffffu, rx0, 1));
        rx0 = fmaxf(rx0, __shfl_xor_sync(0xffffffffu, rx0, 2));
        rx1 = fmaxf(rx1, __shfl_xor_sync(0xffffffffu, rx1, 1));
        rx1 = fmaxf(rx1, __shfl_xor_sync(0xffffffffu, rx1, 2));
        float mn0 = fmaxf(m0, rx0), mn1 = fmaxf(m1, rx1);
        float a0 = __expf(m0 - mn0), a1 = __expf(m1 - mn1);
        m0 = mn0; m1 = mn1;

        float sum0 = 0.f, sum1 = 0.f;
        #pragma unroll
        for (int p = 0; p < 4; p++)
            #pragma unroll
            for (int f = 0; f < 2; f++) {
                float p0 = __expf(s[p][f][0] - mn0);
                float p1 = __expf(s[p][f][1] - mn0);
                float p2 = __expf(s[p][f][2] - mn1);
                float p3 = __expf(s[p][f][3] - mn1);
                s[p][f][0] = p0; s[p][f][1] = p1; s[p][f][2] = p2; s[p][f][3] = p3;
                sum0 += p0 + p1; sum1 += p2 + p3;
            }
        sum0 += __shfl_xor_sync(0xffffffffu, sum0, 1);
        sum0 += __shfl_xor_sync(0xffffffffu, sum0, 2);
        sum1 += __shfl_xor_sync(0xffffffffu, sum1, 1);
        sum1 += __shfl_xor_sync(0xffffffffu, sum1, 2);
        l0 = l0 * a0 + sum0;
        l1 = l1 * a1 + sum1;
        #pragma unroll
        for (int pd = 0; pd < 4; pd++)
            #pragma unroll
            for (int f = 0; f < 2; f++) {
                o[pd][f][0] *= a0; o[pd][f][1] *= a0;
                o[pd][f][2] *= a1; o[pd][f][3] *= a1;
            }

        #pragma unroll
        for (int kc = 0; kc < 4; kc++) {
            uint32_t pah[4], pal[4];
            #pragma unroll
            for (int f = 0; f < 2; f++) {
                float x0 = s[kc][f][0], x1 = s[kc][f][1];
                float x2 = s[kc][f][2], x3 = s[kc][f][3];
                uint32_t h01 = packbf2(x0, x1);
                uint32_t h23 = packbf2(x2, x3);
                __nv_bfloat162 hb01 = *(__nv_bfloat162*)&h01;
                __nv_bfloat162 hb23 = *(__nv_bfloat162*)&h23;
                uint32_t lo01 = packbf2(x0 - __bfloat162float(hb01.x),
                                        x1 - __bfloat162float(hb01.y));
                uint32_t lo23 = packbf2(x2 - __bfloat162float(hb23.x),
                                        x3 - __bfloat162float(hb23.y));
                pah[f * 2 + 0] = h01;  pal[f * 2 + 0] = lo01;
                pah[f * 2 + 1] = h23;  pal[f * 2 + 1] = lo23;
            }
            #pragma unroll
            for (int pd = 0; pd < 4; pd++) {
                uint32_t vf[4], vg[4];
                uint32_t a = sVh + (pd * 16 + bn) * 144 + kc * 32 + bkh;
                ldsm4(vf, a);
                ldsm4(vg, a + AMAT);
                mma_bf16(o[pd][0], pah, &vf[0]);
                mma_bf16(o[pd][1], pah, &vf[2]);
                mma_bf16(o[pd][0], pah, &vg[0]);
                mma_bf16(o[pd][1], pah, &vg[2]);
                mma_bf16(o[pd][0], pal, &vf[0]);
                mma_bf16(o[pd][1], pal, &vf[2]);
            }
        }
    }

    float inv0 = 1.0f / l0, inv1 = 1.0f / l1;
    int b_ = bh >> 4, hh = bh & 15;
    #pragma unroll
    for (int pd = 0; pd < 4; pd++)
        #pragma unroll
        for (int f = 0; f < 2; f++) {
            int dh = pd * 16 + f * 8 + (lane & 3) * 2;
            size_t i0 = ((size_t)(b_ * Ssz + r0g)) * Dsz + hh * 64 + dh;
            size_t i1 = i0 + (size_t)8 * Dsz;
            float2 x0 = *(const float2*)&x[i0];
            float2 x1 = *(const float2*)&x[i1];
            *(float2*)&out[i0] = make_float2(x0.x + o[pd][f][0] * inv0,
                                             x0.y + o[pd][f][1] * inv0);
            *(float2*)&out[i1] = make_float2(x1.x + o[pd][f][2] * inv1,
                                             x1.y + o[pd][f][3] * inv1);
        }
}

// ---------------- launch --------------------------------------------------------
extern "C" void kernel_launch(void* const* d_in, const int* in_sizes, int n_in,
                              void* d_out, int out_size)
{
    const float* x    = (const float*)d_in[0];
    const float* Wq   = (const float*)d_in[1];
    const float* bq   = (const float*)d_in[2];
    const float* Wk   = (const float*)d_in[3];
    const float* bk   = (const float*)d_in[4];
    const float* Wv   = (const float*)d_in[5];
    const float* bv   = (const float*)d_in[6];
    const float* ln1g = (const float*)d_in[7];
    const float* ln1b = (const float*)d_in[8];
    const float* ln2g = (const float*)d_in[9];
    const float* ln2b = (const float*)d_in[10];
    const float* W1   = (const float*)d_in[11];
    const float* b1   = (const float*)d_in[12];
    const float* W2   = (const float*)d_in[13];
    const float* b2   = (const float*)d_in[14];
    float* out = (float*)d_out;

    bf16 *hhi, *hlo, *midhi, *midlo, *wqkvh, *wqkvl, *w1h, *w1l, *w2h, *w2l;
    bf16 *qh_, *ql_, *kh_, *kl_, *vth_, *vtl_;
    cudaGetSymbolAddress((void**)&hhi,   g_hhi);
    cudaGetSymbolAddress((void**)&hlo,   g_hlo);
    cudaGetSymbolAddress((void**)&midhi, g_midhi);
    cudaGetSymbolAddress((void**)&midlo, g_midlo);
    cudaGetSymbolAddress((void**)&wqkvh, g_wqkvT_hi);
    cudaGetSymbolAddress((void**)&wqkvl, g_wqkvT_lo);
    cudaGetSymbolAddress((void**)&w1h,   g_w1T_hi);
    cudaGetSymbolAddress((void**)&w1l,   g_w1T_lo);
    cudaGetSymbolAddress((void**)&w2h,   g_w2T_hi);
    cudaGetSymbolAddress((void**)&w2l,   g_w2T_lo);
    cudaGetSymbolAddress((void**)&qh_,   g_qh);
    cudaGetSymbolAddress((void**)&ql_,   g_ql);
    cudaGetSymbolAddress((void**)&kh_,   g_kh);
    cudaGetSymbolAddress((void**)&kl_,   g_kl);
    cudaGetSymbolAddress((void**)&vth_,  g_vth);
    cudaGetSymbolAddress((void**)&vtl_,  g_vtl);

    cudaFuncSetAttribute(gemm_mma<0>, cudaFuncAttributeMaxDynamicSharedMemorySize, GSMEM);
    cudaFuncSetAttribute(gemm_mma<1>, cudaFuncAttributeMaxDynamicSharedMemorySize, GSMEM);
    cudaFuncSetAttribute(gemm_mma<2>, cudaFuncAttributeMaxDynamicSharedMemorySize, GSMEM);
    cudaFuncSetAttribute(attn_mma, cudaFuncAttributeMaxDynamicSharedMemorySize, ASMEM);

    // weight prep (tight grids: QKV fused, W1, W2)
    trans_split_qkv<<<dim3(Dsz/32, DHsz/32, 48), 256>>>(Wq, Wk, Wv, wqkvh, wqkvl);
    trans_split<<<dim3(Dsz/32, FFsz/32, 1),  256>>>(W1, w1h, w1l, Dsz, FFsz);
    trans_split<<<dim3(FFsz/32, Dsz/32, 1),  256>>>(W2, w2h, w2l, FFsz, Dsz);

    // 1) LN1 -> bf16 split
    ln_split<<<Mrows, 256>>>(x, ln1g, ln1b, hhi, hlo);

    // 2) fused QKV GEMM (N = 3072) -> bf16 q/k + transposed v (bias selected inline)
    gemm_mma<0><<<dim3(3*Dsz/128, Mrows/128), 256, GSMEM>>>(
        hhi, hlo, wqkvh, wqkvl, bq, bk, bv, nullptr, nullptr, nullptr,
        qh_, ql_, kh_, kl_, vth_, vtl_, 3*Dsz, Dsz);

    // 3) tensor-core attention + residual -> out = x1
    attn_mma<<<dim3(Ssz/64, BH), 128, ASMEM>>>(qh_, ql_, kh_, kl_, vth_, vtl_, x, out);

    // 4) LN2 -> bf16 split
    ln_split<<<Mrows, 256>>>(out, ln2g, ln2b, hhi, hlo);

    // 5) mid = GELU(h @ W1 + b1), split to bf16
    gemm_mma<1><<<dim3(FFsz/128, Mrows/128), 256, GSMEM>>>(
        hhi, hlo, w1h, w1l, b1, nullptr, nullptr, nullptr, midhi, midlo,
        nullptr, nullptr, nullptr, nullptr, nullptr, nullptr, FFsz, Dsz);

    // 6) out = x1 + mid @ W2 + b2
    gemm_mma<2><<<dim3(Dsz/128, Mrows/128), 256, GSMEM>>>(
        midhi, midlo, w2h, w2l, b2, nullptr, nullptr, out, nullptr, nullptr,
        nullptr, nullptr, nullptr, nullptr, nullptr, nullptr, Dsz, FFsz);
}

// round 16
// speedup vs baseline: 1.3402x; 1.0090x over previous
#include <cuda_runtime.h>
#include <cuda_bf16.h>
#include <math.h>
#include <stdint.h>

#define Bsz 2
#define Ssz 2048
#define Dsz 1024
#define Hsz 16
#define DHsz 64
#define FFsz 4096
#define Mrows (Bsz*Ssz)   // 4096
#define BH    (Bsz*Hsz)   // 32

typedef __nv_bfloat16 bf16;

// ---------------- scratch (device globals) ----------------------------------
__device__ bf16  g_hhi[Mrows * Dsz];
__device__ bf16  g_hlo[Mrows * Dsz];
__device__ bf16  g_midhi[(size_t)Mrows * FFsz];
__device__ bf16  g_midlo[(size_t)Mrows * FFsz];
__device__ bf16  g_wqkvT_hi[3 * Dsz * Dsz];
__device__ bf16  g_wqkvT_lo[3 * Dsz * Dsz];
__device__ bf16  g_w1T_hi[FFsz * Dsz];
__device__ bf16  g_w1T_lo[FFsz * Dsz];
__device__ bf16  g_w2T_hi[Dsz * FFsz];
__device__ bf16  g_w2T_lo[Dsz * FFsz];
__device__ bf16  g_qh[BH * Ssz * DHsz];
__device__ bf16  g_ql[BH * Ssz * DHsz];
__device__ bf16  g_kh[BH * Ssz * DHsz];
__device__ bf16  g_kl[BH * Ssz * DHsz];
__device__ bf16  g_vth[BH * DHsz * Ssz];   // transposed: [bh][dh][s]
__device__ bf16  g_vtl[BH * DHsz * Ssz];

// ---------------- PTX helpers -------------------------------------------------
__device__ __forceinline__ uint32_t smem_u32(const void* p) {
    uint32_t a;
    asm("{ .reg .u64 t; cvta.to.shared.u64 t, %1; cvt.u32.u64 %0, t; }" : "=r"(a) : "l"(p));
    return a;
}
__device__ __forceinline__ void cp16(uint32_t dst, const void* src) {
    asm volatile("cp.async.cg.shared.global [%0], [%1], 16;" :: "r"(dst), "l"(src));
}
__device__ __forceinline__ void cp_commit() { asm volatile("cp.async.commit_group;"); }
__device__ __forceinline__ void cp_wait1()  { asm volatile("cp.async.wait_group 1;" ::: "memory"); }
__device__ __forceinline__ void cp_wait0()  { asm volatile("cp.async.wait_group 0;" ::: "memory"); }

__device__ __forceinline__ void ldsm4(uint32_t* r, uint32_t addr) {
    asm volatile("ldmatrix.sync.aligned.m8n8.x4.shared.b16 {%0,%1,%2,%3}, [%4];"
        : "=r"(r[0]), "=r"(r[1]), "=r"(r[2]), "=r"(r[3]) : "r"(addr));
}
// Non-volatile — pure register op; lets ptxas interleave MMAs with ldsm.
__device__ __forceinline__ void mma_bf16(float* d, const uint32_t* a, const uint32_t* b) {
    asm("mma.sync.aligned.m16n8k16.row.col.f32.bf16.bf16.f32 "
        "{%0,%1,%2,%3}, {%4,%5,%6,%7}, {%8,%9}, {%0,%1,%2,%3};"
        : "+f"(d[0]), "+f"(d[1]), "+f"(d[2]), "+f"(d[3])
        : "r"(a[0]), "r"(a[1]), "r"(a[2]), "r"(a[3]), "r"(b[0]), "r"(b[1]));
}

__device__ __forceinline__ float gelu_exact(float v) {
    return 0.5f * v * (1.0f + erff(v * 0.70710678118654752f));
}
struct __align__(8) bf4 { bf16 a, b, c, d; };
struct __align__(4) bf2 { bf16 a, b; };

__device__ __forceinline__ uint32_t packbf2(float a, float b) {
    __nv_bfloat162 t = __float22bfloat162_rn(make_float2(a, b));
    return *(uint32_t*)&t;
}

// ---------------- LayerNorm -> bf16 hi/lo split -------------------------------
__global__ void __launch_bounds__(256) ln_split(const float* __restrict__ x,
                                                const float* __restrict__ g,
                                                const float* __restrict__ beta,
                                                bf16* __restrict__ hi,
                                                bf16* __restrict__ lo)
{
    int row = blockIdx.x;
    int t   = threadIdx.x;
    float4 xv = ((const float4*)(x + (size_t)row * Dsz))[t];
    float s  = xv.x + xv.y + xv.z + xv.w;
    float ss = xv.x*xv.x + xv.y*xv.y + xv.z*xv.z + xv.w*xv.w;
    #pragma unroll
    for (int o = 16; o; o >>= 1) {
        s  += __shfl_xor_sync(0xffffffffu, s,  o);
        ss += __shfl_xor_sync(0xffffffffu, ss, o);
    }
    __shared__ float sh[16];
    int w = t >> 5;
    if ((t & 31) == 0) { sh[w] = s; sh[8 + w] = ss; }
    __syncthreads();
    s = 0.f; ss = 0.f;
    #pragma unroll
    for (int i = 0; i < 8; i++) { s += sh[i]; ss += sh[8 + i]; }
    float mu  = s * (1.0f / Dsz);
    float var = ss * (1.0f / Dsz) - mu * mu;
    float inv = rsqrtf(var + 1e-5f);
    float4 gv = ((const float4*)g)[t];
    float4 bv = ((const float4*)beta)[t];
    float r[4];
    r[0] = (xv.x - mu) * inv * gv.x + bv.x;
    r[1] = (xv.y - mu) * inv * gv.y + bv.y;
    r[2] = (xv.z - mu) * inv * gv.z + bv.z;
    r[3] = (xv.w - mu) * inv * gv.w + bv.w;
    bf16 h4[4], l4[4];
    #pragma unroll
    for (int i = 0; i < 4; i++) {
        h4[i] = __float2bfloat16_rn(r[i]);
        l4[i] = __float2bfloat16_rn(r[i] - __bfloat162float(h4[i]));
    }
    size_t off = (size_t)row * Dsz + t * 4;
    *(bf4*)(hi + off) = bf4{h4[0], h4[1], h4[2], h4[3]};
    *(bf4*)(lo + off) = bf4{l4[0], l4[1], l4[2], l4[3]};
}

// ---------------- transpose + split: in[Kd, segN] -> out[rowBase+n][Kd] --------
__device__ __forceinline__ void trans_split_body(const float* __restrict__ ib,
                                                 bf16* __restrict__ oh,
                                                 bf16* __restrict__ ol,
                                                 int Kd, int segN,
                                                 int k0, int n0, size_t rowBase,
                                                 int tx, int ty, float s[32][33])
{
    #pragma unroll
    for (int ii = 0; ii < 4; ii++)
        s[ty + ii * 8][tx] = ib[(size_t)(k0 + ty + ii * 8) * segN + n0 + tx];
    __syncthreads();
    #pragma unroll
    for (int ii = 0; ii < 4; ii++) {
        int n = n0 + ty + ii * 8;
        float v = s[tx][ty + ii * 8];
        bf16 h = __float2bfloat16_rn(v);
        bf16 l = __float2bfloat16_rn(v - __bfloat162float(h));
        size_t o = (rowBase + n) * (size_t)Kd + k0 + tx;
        oh[o] = h; ol[o] = l;
    }
}

__global__ void __launch_bounds__(256) trans_split(const float* __restrict__ in,
                                                   bf16* __restrict__ oh,
                                                   bf16* __restrict__ ol,
                                                   int Kd, int segN)
{
    __shared__ float s[32][33];
    int k0 = blockIdx.x * 32, n0 = blockIdx.y * 32, z = blockIdx.z;
    trans_split_body(in + (size_t)z * Kd * segN, oh, ol, Kd, segN,
                     k0, n0, (size_t)z * segN,
                     threadIdx.x & 31, threadIdx.x >> 5, s);
}

// fused QKV weight prep: z in [0,48): seg = z>>4 (q/k/v), head = z&15
__global__ void __launch_bounds__(256) trans_split_qkv(const float* __restrict__ Wq,
                                                       const float* __restrict__ Wk,
                                                       const float* __restrict__ Wv,
                                                       bf16* __restrict__ oh,
                                                       bf16* __restrict__ ol)
{
    __shared__ float s[32][33];
    int k0 = blockIdx.x * 32, n0 = blockIdx.y * 32, z = blockIdx.z;
    int seg = z >> 4, head = z & 15;
    const float* W = (seg == 0) ? Wq : (seg == 1) ? Wk : Wv;
    trans_split_body(W + (size_t)head * Dsz * DHsz,
                     oh + (size_t)seg * Dsz * Dsz, ol + (size_t)seg * Dsz * Dsz,
                     Dsz, DHsz, k0, n0, (size_t)head * DHsz,
                     threadIdx.x & 31, threadIdx.x >> 5, s);
}

// ---------------- mma.sync GEMM, bf16-split 3-pass (round-7 proven config) -----
// 128x128 CTA tile, 8 warps (4m x 2n), warp tile 32x64, K-slab 32, 2-stage.
// __launch_bounds__(256,2) forces <=128 regs -> guaranteed 2 CTAs/SM.
#define MATB   10240
#define STAGEB (4*MATB)
#define GSMEM  (2*STAGEB)   // 81920

template<int MODE>
__global__ void __launch_bounds__(256, 2) gemm_mma(
    const bf16* __restrict__ Ahi, const bf16* __restrict__ Alo,
    const bf16* __restrict__ Bhi, const bf16* __restrict__ Blo,
    const float* __restrict__ bias,          // MODE 1/2; MODE 0: q bias
    const float* __restrict__ biasK,         // MODE 0 only
    const float* __restrict__ biasV,         // MODE 0 only
    float* __restrict__ O0,
    bf16* __restrict__ OH, bf16* __restrict__ OL,
    bf16* __restrict__ Qh, bf16* __restrict__ Ql,
    bf16* __restrict__ Kh, bf16* __restrict__ Kl,
    bf16* __restrict__ Vh, bf16* __restrict__ Vl,
    int N, int K)
{
    extern __shared__ __align__(1024) char smem[];
    uint32_t sb = smem_u32(smem);
    int tid = threadIdx.x, wid = tid >> 5, lane = tid & 31;
    int m0 = blockIdx.y * 128, n0 = blockIdx.x * 128;
    int wm = (wid & 3) * 32, wn = (wid >> 2) * 64;

    const char* gbase[4] = {
        (const char*)(Ahi + (size_t)m0 * K),
        (const char*)(Alo + (size_t)m0 * K),
        (const char*)(Bhi + (size_t)n0 * K),
        (const char*)(Blo + (size_t)n0 * K)};
    const size_t ldb = (size_t)K * 2;

    const int lrow = tid >> 1;           // 0..127
    const int lcc  = (tid & 1) * 32;     // byte col within 64B slab row

    float acc[2][8][4];
    #pragma unroll
    for (int t = 0; t < 2; t++)
        #pragma unroll
        for (int j = 0; j < 8; j++)
            #pragma unroll
            for (int q = 0; q < 4; q++) acc[t][j][q] = 0.f;

    int nslab = K >> 5;

    // ---- prologue: load stage 0
    {
        uint32_t stg = sb;
        #pragma unroll
        for (int mat = 0; mat < 4; mat++) {
            const char* g = gbase[mat] + (size_t)lrow * ldb + lcc;
            uint32_t dst = stg + mat * MATB + lrow * 80 + lcc;
            cp16(dst, g); cp16(dst + 16, g + 16);
        }
        cp_commit();
    }

    const int arow = lane & 15;
    const int akh  = (lane >> 4) * 16;
    const int bn   = ((lane >> 4) & 1) * 8 + (lane & 7);
    const int bkh  = ((lane >> 3) & 1) * 16;

    for (int s = 0; s < nslab; ++s) {
        uint32_t stg = sb + (s & 1) * STAGEB;
        if (s + 1 < nslab) {
            uint32_t nstg = sb + ((s + 1) & 1) * STAGEB;
            #pragma unroll
            for (int mat = 0; mat < 4; mat++) {
                const char* g = gbase[mat] + (size_t)lrow * ldb + (size_t)(s + 1) * 64 + lcc;
                uint32_t dst = nstg + mat * MATB + lrow * 80 + lcc;
                cp16(dst, g); cp16(dst + 16, g + 16);
            }
            cp_commit();
            cp_wait1();
        } else {
            cp_wait0();
        }
        __syncthreads();

        #pragma unroll
        for (int ks = 0; ks < 2; ks++) {
            int kb = ks * 32;
            uint32_t ah[8], al[8];
            #pragma unroll
            for (int t = 0; t < 2; t++) {
                uint32_t ra = stg + (wm + t * 16 + arow) * 80 + kb + akh;
                ldsm4(&ah[t * 4], ra);
                ldsm4(&al[t * 4], ra + MATB);
            }
            #pragma unroll
            for (int p = 0; p < 4; p++) {
                uint32_t rb = stg + 2 * MATB + (wn + p * 16 + bn) * 80 + kb + bkh;
                uint32_t bh[4], bl[4];
                ldsm4(bh, rb);
                ldsm4(bl, rb + MATB);
                #pragma unroll
                for (int t = 0; t < 2; t++) {
                    mma_bf16(acc[t][p*2+0], &ah[t*4], &bh[0]);
                    mma_bf16(acc[t][p*2+1], &ah[t*4], &bh[2]);
                    mma_bf16(acc[t][p*2+0], &ah[t*4], &bl[0]);
                    mma_bf16(acc[t][p*2+1], &ah[t*4], &bl[2]);
                    mma_bf16(acc[t][p*2+0], &al[t*4], &bh[0]);
                    mma_bf16(acc[t][p*2+1], &al[t*4], &bh[2]);
                }
            }
        }
        __syncthreads();
    }

    // ---- epilogue: direct fragment stores
    int g2 = lane >> 2, c2 = (lane & 3) * 2;
    #pragma unroll
    for (int t = 0; t < 2; t++) {
        #pragma unroll
        for (int j = 0; j < 8; j++) {
            int m = m0 + wm + t * 16 + g2;
            int n = n0 + wn + j * 8 + c2;
            float b0, b1;
            if (MODE == 0) {
                const float* bsel = (n < 1024) ? bias : (n < 2048) ? biasK : biasV;
                b0 = bsel[n & 1023]; b1 = bsel[(n & 1023) + 1];
            } else {
                b0 = bias[n]; b1 = bias[n + 1];
            }
            float v00 = acc[t][j][0] + b0, v01 = acc[t][j][1] + b1;
            float v10 = acc[t][j][2] + b0, v11 = acc[t][j][3] + b1;
            if (MODE == 0) {
                int which = n >> 10, hh = (n >> 6) & 15, e = n & 63;
                int b_ = m >> 11, s0 = m & 2047;
                bf16 h00 = __float2bfloat16_rn(v00), h01 = __float2bfloat16_rn(v01);
                bf16 h10 = __float2bfloat16_rn(v10), h11 = __float2bfloat16_rn(v11);
                bf16 l00 = __float2bfloat16_rn(v00 - __bfloat162float(h00));
                bf16 l01 = __float2bfloat16_rn(v01 - __bfloat162float(h01));
                bf16 l10 = __float2bfloat16_rn(v10 - __bfloat162float(h10));
                bf16 l11 = __float2bfloat16_rn(v11 - __bfloat162float(h11));
                if (which < 2) {
                    bf16* dh_ = (which == 0) ? Qh : Kh;
                    bf16* dl_ = (which == 0) ? Ql : Kl;
                    size_t base = ((size_t)(b_ * Hsz + hh) * Ssz + s0) * 64 + e;
                    *(bf2*)&dh_[base] = bf2{h00, h01};
                    *(bf2*)&dl_[base] = bf2{l00, l01};
                    *(bf2*)&dh_[base + 8 * 64] = bf2{h10, h11};
                    *(bf2*)&dl_[base + 8 * 64] = bf2{l10, l11};
                } else {
                    size_t base = ((size_t)(b_ * Hsz + hh) * 64 + e) * Ssz + s0;
                    Vh[base]            = h00;  Vl[base]            = l00;
                    Vh[base + Ssz]      = h01;  Vl[base + Ssz]      = l01;
                    Vh[base + 8]        = h10;  Vl[base + 8]        = l10;
                    Vh[base + Ssz + 8]  = h11;  Vl[base + Ssz + 8]  = l11;
                }
            } else if (MODE == 1) {
                v00 = gelu_exact(v00); v01 = gelu_exact(v01);
                v10 = gelu_exact(v10); v11 = gelu_exact(v11);
                bf16 h00 = __float2bfloat16_rn(v00), h01 = __float2bfloat16_rn(v01);
                bf16 h10 = __float2bfloat16_rn(v10), h11 = __float2bfloat16_rn(v11);
                bf16 l00 = __float2bfloat16_rn(v00 - __bfloat162float(h00));
                bf16 l01 = __float2bfloat16_rn(v01 - __bfloat162float(h01));
                bf16 l10 = __float2bfloat16_rn(v10 - __bfloat162float(h10));
                bf16 l11 = __float2bfloat16_rn(v11 - __bfloat162float(h11));
                size_t r0 = (size_t)m * N + n, r1 = (size_t)(m + 8) * N + n;
                *(bf2*)&OH[r0] = bf2{h00, h01};
                *(bf2*)&OH[r1] = bf2{h10, h11};
                *(bf2*)&OL[r0] = bf2{l00, l01};
                *(bf2*)&OL[r1] = bf2{l10, l11};
            } else {
                size_t r0 = (size_t)m * N + n, r1 = (size_t)(m + 8) * N + n;
                float2 c0 = *(float2*)&O0[r0];
                float2 c1 = *(float2*)&O0[r1];
                *(float2*)&O0[r0] = make_float2(v00 + c0.x, v01 + c0.y);
                *(float2*)&O0[r1] = make_float2(v10 + c1.x, v11 + c1.y);
            }
        }
    }
}

// ---------------- tensor-core flash attention (causal) -------------------------
// Round-13 structure; K and V committed as separate cp.async groups so the
// V-load tail overlaps the S/softmax phase (no smem/reg/occupancy change).
#define AMAT 9216
#define ASMEM (6*AMAT)   // Qh Ql Kh Kl Vth Vtl = 55296

__global__ void __launch_bounds__(128, 3) attn_mma(
    const bf16* __restrict__ qh, const bf16* __restrict__ ql,
    const bf16* __restrict__ kh, const bf16* __restrict__ kl,
    const bf16* __restrict__ vth, const bf16* __restrict__ vtl,
    const float* __restrict__ x, float* __restrict__ out)
{
    extern __shared__ __align__(1024) char asmem[];
    uint32_t sb = smem_u32(asmem);
    const uint32_t sQh = sb, sKh = sb + 2*AMAT, sVh = sb + 4*AMAT;

    int tid = threadIdx.x, lane = tid & 31, wid = tid >> 5;
    int bh = blockIdx.y;
    int qt = gridDim.x - 1 - blockIdx.x;
    int q0 = qt * 64;
    int wm = wid * 16;

    const bf16* qhg = qh + ((size_t)bh * Ssz + q0) * 64;
    const bf16* qlg = ql + ((size_t)bh * Ssz + q0) * 64;
    const bf16* khg = kh + (size_t)bh * Ssz * 64;
    const bf16* klg = kl + (size_t)bh * Ssz * 64;
    const bf16* vthg = vth + (size_t)bh * 64 * Ssz;
    const bf16* vtlg = vtl + (size_t)bh * 64 * Ssz;

    #pragma unroll
    for (int i = 0; i < 4; i++) {
        int ch = i * 128 + tid;
        int r = ch >> 3, c = (ch & 7) * 16;
        cp16(sQh + r * 144 + c, (const char*)qhg + r * 128 + c);
        cp16(sQh + AMAT + r * 144 + c, (const char*)qlg + r * 128 + c);
    }
    cp_commit(); cp_wait0(); __syncthreads();

    const int arow = lane & 15;
    const int akh  = (lane >> 4) * 16;
    const int bn   = ((lane >> 4) & 1) * 8 + (lane & 7);
    const int bkh  = ((lane >> 3) & 1) * 16;

    uint32_t qfh[4][4], qfl[4][4];
    #pragma unroll
    for (int kc = 0; kc < 4; kc++) {
        uint32_t a = sQh + (wm + arow) * 144 + kc * 32 + akh;
        ldsm4(qfh[kc], a);
        ldsm4(qfl[kc], a + AMAT);
    }

    float m0 = -1e30f, m1 = -1e30f, l0 = 0.f, l1 = 0.f;
    float o[4][2][4];
    #pragma unroll
    for (int pd = 0; pd < 4; pd++)
        #pragma unroll
        for (int f = 0; f < 2; f++)
            #pragma unroll
            for (int e = 0; e < 4; e++) o[pd][f][e] = 0.f;

    int r0g = q0 + wm + (lane >> 2);
    int ntiles = qt + 1;

    for (int t = 0; t < ntiles; t++) {
        int j0 = t * 64;
        __syncthreads();   // prior tile compute done before refill
        // K group (committed first)
        #pragma unroll
        for (int i = 0; i < 4; i++) {
            int ch = i * 128 + tid;
            int r = ch >> 3, c = (ch & 7) * 16;
            cp16(sKh + r * 144 + c,        (const char*)(khg + (size_t)(j0 + r) * 64) + c);
            cp16(sKh + AMAT + r * 144 + c, (const char*)(klg + (size_t)(j0 + r) * 64) + c);
        }
        cp_commit();
        // V group (in flight during S/softmax)
        #pragma unroll
        for (int i = 0; i < 4; i++) {
            int ch = i * 128 + tid;
            int r = ch >> 3, c = (ch & 7) * 16;
            cp16(sVh + r * 144 + c,        (const char*)(vthg + (size_t)r * Ssz + j0) + c);
            cp16(sVh + AMAT + r * 144 + c, (const char*)(vtlg + (size_t)r * Ssz + j0) + c);
        }
        cp_commit();
        cp_wait1();        // K resident; V may still fly
        __syncthreads();

        float s[4][2][4];
        #pragma unroll
        for (int p = 0; p < 4; p++)
            #pragma unroll
            for (int f = 0; f < 2; f++)
                #pragma unroll
                for (int e = 0; e < 4; e++) s[p][f][e] = 0.f;

        #pragma unroll
        for (int kc = 0; kc < 4; kc++) {
            #pragma unroll
            for (int p = 0; p < 4; p++) {
                uint32_t kf[4], kg[4];
                uint32_t a = sKh + (p * 16 + bn) * 144 + kc * 32 + bkh;
                ldsm4(kf, a);
                ldsm4(kg, a + AMAT);
                mma_bf16(s[p][0], qfh[kc], &kf[0]);
                mma_bf16(s[p][1], qfh[kc], &kf[2]);
                mma_bf16(s[p][0], qfh[kc], &kg[0]);
                mma_bf16(s[p][1], qfh[kc], &kg[2]);
                mma_bf16(s[p][0], qfl[kc], &kf[0]);
                mma_bf16(s[p][1], qfl[kc], &kf[2]);
            }
        }

        bool diag = (j0 == q0);
        #pragma unroll
        for (int p = 0; p < 4; p++)
            #pragma unroll
            for (int f = 0; f < 2; f++) {
                int colb = j0 + p * 16 + f * 8 + (lane & 3) * 2;
                #pragma unroll
                for (int e = 0; e < 4; e++) {
                    float sv = s[p][f][e] * 0.125f;
                    if (diag) {
                        int col = colb + (e & 1);
                        int row = r0g + ((e >> 1) << 3);
                        if (col > row) sv = -1e30f;
                    }
                    s[p][f][e] = sv;
                }
            }

        float rx0 = -1e30f, rx1 = -1e30f;
        #pragma unroll
        for (int p = 0; p < 4; p++)
            #pragma unroll
            for (int f = 0; f < 2; f++) {
                rx0 = fmaxf(rx0, fmaxf(s[p][f][0], s[p][f][1]));
                rx1 = fmaxf(rx1, fmaxf(s[p][f][2], s[p][f][3]));
            }
        rx0 = fmaxf(rx0, __shfl_xor_sync(0xffffffffu, rx0, 1));
        rx0 = fmaxf(rx0, __shfl_xor_sync(0xffffffffu, rx0, 2));
        rx1 = fmaxf(rx1, __shfl_xor_sync(0xffffffffu, rx1, 1));
        rx1 = fmaxf(rx1, __shfl_xor_sync(0xffffffffu, rx1, 2));
        float mn0 = fmaxf(m0, rx0), mn1 = fmaxf(m1, rx1);
        float a0 = __expf(m0 - mn0), a1 = __expf(m1 - mn1);
        m0 = mn0; m1 = mn1;

        float sum0 = 0.f, sum1 = 0.f;
        #pragma unroll
        for (int p = 0; p < 4; p++)
            #pragma unroll
            for (int f = 0; f < 2; f++) {
                float p0 = __expf(s[p][f][0] - mn0);
                float p1 = __expf(s[p][f][1] - mn0);
                float p2 = __expf(s[p][f][2] - mn1);
                float p3 = __expf(s[p][f][3] - mn1);
                s[p][f][0] = p0; s[p][f][1] = p1; s[p][f][2] = p2; s[p][f][3] = p3;
                sum0 += p0 + p1; sum1 += p2 + p3;
            }
        sum0 += __shfl_xor_sync(0xffffffffu, sum0, 1);
        sum0 += __shfl_xor_sync(0xffffffffu, sum0, 2);
        sum1 += __shfl_xor_sync(0xffffffffu, sum1, 1);
        sum1 += __shfl_xor_sync(0xffffffffu, sum1, 2);
        l0 = l0 * a0 + sum0;
        l1 = l1 * a1 + sum1;
        #pragma unroll
        for (int pd = 0; pd < 4; pd++)
            #pragma unroll
            for (int f = 0; f < 2; f++) {
                o[pd][f][0] *= a0; o[pd][f][1] *= a0;
                o[pd][f][2] *= a1; o[pd][f][3] *= a1;
            }

        cp_wait0();        // V resident
        __syncthreads();

        #pragma unroll
        for (int kc = 0; kc < 4; kc++) {
            uint32_t pah[4], pal[4];
            #pragma unroll
            for (int f = 0; f < 2; f++) {
                float x0 = s[kc][f][0], x1 = s[kc][f][1];
                float x2 = s[kc][f][2], x3 = s[kc][f][3];
                uint32_t h01 = packbf2(x0, x1);
                uint32_t h23 = packbf2(x2, x3);
                __nv_bfloat162 hb01 = *(__nv_bfloat162*)&h01;
                __nv_bfloat162 hb23 = *(__nv_bfloat162*)&h23;
                uint32_t lo01 = packbf2(x0 - __bfloat162float(hb01.x),
                                        x1 - __bfloat162float(hb01.y));
                uint32_t lo23 = packbf2(x2 - __bfloat162float(hb23.x),
                                        x3 - __bfloat162float(hb23.y));
                pah[f * 2 + 0] = h01;  pal[f * 2 + 0] = lo01;
                pah[f * 2 + 1] = h23;  pal[f * 2 + 1] = lo23;
            }
            #pragma unroll
            for (int pd = 0; pd < 4; pd++) {
                uint32_t vf[4], vg[4];
                uint32_t a = sVh + (pd * 16 + bn) * 144 + kc * 32 + bkh;
                ldsm4(vf, a);
                ldsm4(vg, a + AMAT);
                mma_bf16(o[pd][0], pah, &vf[0]);
                mma_bf16(o[pd][1], pah, &vf[2]);
                mma_bf16(o[pd][0], pah, &vg[0]);
                mma_bf16(o[pd][1], pah, &vg[2]);
                mma_bf16(o[pd][0], pal, &vf[0]);
                mma_bf16(o[pd][1], pal, &vf[2]);
            }
        }
    }

    float inv0 = 1.0f / l0, inv1 = 1.0f / l1;
    int b_ = bh >> 4, hh = bh & 15;
    #pragma unroll
    for (int pd = 0; pd < 4; pd++)
        #pragma unroll
        for (int f = 0; f < 2; f++) {
            int dh = pd * 16 + f * 8 + (lane & 3) * 2;
            size_t i0 = ((size_t)(b_ * Ssz + r0g)) * Dsz + hh * 64 + dh;
            size_t i1 = i0 + (size_t)8 * Dsz;
            float2 x0 = *(const float2*)&x[i0];
            float2 x1 = *(const float2*)&x[i1];
            *(float2*)&out[i0] = make_float2(x0.x + o[pd][f][0] * inv0,
                                             x0.y + o[pd][f][1] * inv0);
            *(float2*)&out[i1] = make_float2(x1.x + o[pd][f][2] * inv1,
                                             x1.y + o[pd][f][3] * inv1);
        }
}

// ---------------- launch --------------------------------------------------------
extern "C" void kernel_launch(void* const* d_in, const int* in_sizes, int n_in,
                              void* d_out, int out_size)
{
    const float* x    = (const float*)d_in[0];
    const float* Wq   = (const float*)d_in[1];
    const float* bq   = (const float*)d_in[2];
    const float* Wk   = (const float*)d_in[3];
    const float* bk   = (const float*)d_in[4];
    const float* Wv   = (const float*)d_in[5];
    const float* bv   = (const float*)d_in[6];
    const float* ln1g = (const float*)d_in[7];
    const float* ln1b = (const float*)d_in[8];
    const float* ln2g = (const float*)d_in[9];
    const float* ln2b = (const float*)d_in[10];
    const float* W1   = (const float*)d_in[11];
    const float* b1   = (const float*)d_in[12];
    const float* W2   = (const float*)d_in[13];
    const float* b2   = (const float*)d_in[14];
    float* out = (float*)d_out;

    bf16 *hhi, *hlo, *midhi, *midlo, *wqkvh, *wqkvl, *w1h, *w1l, *w2h, *w2l;
    bf16 *qh_, *ql_, *kh_, *kl_, *vth_, *vtl_;
    cudaGetSymbolAddress((void**)&hhi,   g_hhi);
    cudaGetSymbolAddress((void**)&hlo,   g_hlo);
    cudaGetSymbolAddress((void**)&midhi, g_midhi);
    cudaGetSymbolAddress((void**)&midlo, g_midlo);
    cudaGetSymbolAddress((void**)&wqkvh, g_wqkvT_hi);
    cudaGetSymbolAddress((void**)&wqkvl, g_wqkvT_lo);
    cudaGetSymbolAddress((void**)&w1h,   g_w1T_hi);
    cudaGetSymbolAddress((void**)&w1l,   g_w1T_lo);
    cudaGetSymbolAddress((void**)&w2h,   g_w2T_hi);
    cudaGetSymbolAddress((void**)&w2l,   g_w2T_lo);
    cudaGetSymbolAddress((void**)&qh_,   g_qh);
    cudaGetSymbolAddress((void**)&ql_,   g_ql);
    cudaGetSymbolAddress((void**)&kh_,   g_kh);
    cudaGetSymbolAddress((void**)&kl_,   g_kl);
    cudaGetSymbolAddress((void**)&vth_,  g_vth);
    cudaGetSymbolAddress((void**)&vtl_,  g_vtl);

    cudaFuncSetAttribute(gemm_mma<0>, cudaFuncAttributeMaxDynamicSharedMemorySize, GSMEM);
    cudaFuncSetAttribute(gemm_mma<1>, cudaFuncAttributeMaxDynamicSharedMemorySize, GSMEM);
    cudaFuncSetAttribute(gemm_mma<2>, cudaFuncAttributeMaxDynamicSharedMemorySize, GSMEM);
    cudaFuncSetAttribute(attn_mma, cudaFuncAttributeMaxDynamicSharedMemorySize, ASMEM);

    // weight prep (tight grids: QKV fused, W1, W2)
    trans_split_qkv<<<dim3(Dsz/32, DHsz/32, 48), 256>>>(Wq, Wk, Wv, wqkvh, wqkvl);
    trans_split<<<dim3(Dsz/32, FFsz/32, 1),  256>>>(W1, w1h, w1l, Dsz, FFsz);
    trans_split<<<dim3(FFsz/32, Dsz/32, 1),  256>>>(W2, w2h, w2l, FFsz, Dsz);

    // 1) LN1 -> bf16 split
    ln_split<<<Mrows, 256>>>(x, ln1g, ln1b, hhi, hlo);

    // 2) fused QKV GEMM (N = 3072) -> bf16 q/k + transposed v (bias selected inline)
    gemm_mma<0><<<dim3(3*Dsz/128, Mrows/128), 256, GSMEM>>>(
        hhi, hlo, wqkvh, wqkvl, bq, bk, bv, nullptr, nullptr, nullptr,
        qh_, ql_, kh_, kl_, vth_, vtl_, 3*Dsz, Dsz);

    // 3) tensor-core attention + residual -> out = x1
    attn_mma<<<dim3(Ssz/64, BH), 128, ASMEM>>>(qh_, ql_, kh_, kl_, vth_, vtl_, x, out);

    // 4) LN2 -> bf16 split
    ln_split<<<Mrows, 256>>>(out, ln2g, ln2b, hhi, hlo);

    // 5) mid = GELU(h @ W1 + b1), split to bf16
    gemm_mma<1><<<dim3(FFsz/128, Mrows/128), 256, GSMEM>>>(
        hhi, hlo, w1h, w1l, b1, nullptr, nullptr, nullptr, midhi, midlo,
        nullptr, nullptr, nullptr, nullptr, nullptr, nullptr, FFsz, Dsz);

    // 6) out = x1 + mid @ W2 + b2
    gemm_mma<2><<<dim3(Dsz/128, Mrows/128), 256, GSMEM>>>(
        midhi, midlo, w2h, w2l, b2, nullptr, nullptr, out, nullptr, nullptr,
        nullptr, nullptr, nullptr, nullptr, nullptr, nullptr, Dsz, FFsz);
}

// round 17
// speedup vs baseline: 1.3506x; 1.0077x over previous
#include <cuda_runtime.h>
#include <cuda_bf16.h>
#include <math.h>
#include <stdint.h>

#define Bsz 2
#define Ssz 2048
#define Dsz 1024
#define Hsz 16
#define DHsz 64
#define FFsz 4096
#define Mrows (Bsz*Ssz)   // 4096
#define BH    (Bsz*Hsz)   // 32

typedef __nv_bfloat16 bf16;

// ---------------- scratch (device globals) ----------------------------------
__device__ bf16  g_hhi[Mrows * Dsz];
__device__ bf16  g_hlo[Mrows * Dsz];
__device__ bf16  g_midhi[(size_t)Mrows * FFsz];
__device__ bf16  g_midlo[(size_t)Mrows * FFsz];
__device__ bf16  g_wqkvT_hi[3 * Dsz * Dsz];
__device__ bf16  g_wqkvT_lo[3 * Dsz * Dsz];
__device__ bf16  g_w1T_hi[FFsz * Dsz];
__device__ bf16  g_w1T_lo[FFsz * Dsz];
__device__ bf16  g_w2T_hi[Dsz * FFsz];
__device__ bf16  g_w2T_lo[Dsz * FFsz];
__device__ bf16  g_qh[BH * Ssz * DHsz];
__device__ bf16  g_ql[BH * Ssz * DHsz];
__device__ bf16  g_kh[BH * Ssz * DHsz];
__device__ bf16  g_kl[BH * Ssz * DHsz];
__device__ bf16  g_vth[BH * DHsz * Ssz];   // transposed: [bh][dh][s]
__device__ bf16  g_vtl[BH * DHsz * Ssz];

// ---------------- PTX helpers -------------------------------------------------
__device__ __forceinline__ uint32_t smem_u32(const void* p) {
    uint32_t a;
    asm("{ .reg .u64 t; cvta.to.shared.u64 t, %1; cvt.u32.u64 %0, t; }" : "=r"(a) : "l"(p));
    return a;
}
__device__ __forceinline__ void cp16(uint32_t dst, const void* src) {
    asm volatile("cp.async.cg.shared.global [%0], [%1], 16;" :: "r"(dst), "l"(src));
}
__device__ __forceinline__ void cp_commit() { asm volatile("cp.async.commit_group;"); }
__device__ __forceinline__ void cp_wait1()  { asm volatile("cp.async.wait_group 1;" ::: "memory"); }
__device__ __forceinline__ void cp_wait0()  { asm volatile("cp.async.wait_group 0;" ::: "memory"); }

__device__ __forceinline__ void ldsm4(uint32_t* r, uint32_t addr) {
    asm volatile("ldmatrix.sync.aligned.m8n8.x4.shared.b16 {%0,%1,%2,%3}, [%4];"
        : "=r"(r[0]), "=r"(r[1]), "=r"(r[2]), "=r"(r[3]) : "r"(addr));
}
// Non-volatile — pure register op; lets ptxas interleave MMAs with ldsm.
__device__ __forceinline__ void mma_bf16(float* d, const uint32_t* a, const uint32_t* b) {
    asm("mma.sync.aligned.m16n8k16.row.col.f32.bf16.bf16.f32 "
        "{%0,%1,%2,%3}, {%4,%5,%6,%7}, {%8,%9}, {%0,%1,%2,%3};"
        : "+f"(d[0]), "+f"(d[1]), "+f"(d[2]), "+f"(d[3])
        : "r"(a[0]), "r"(a[1]), "r"(a[2]), "r"(a[3]), "r"(b[0]), "r"(b[1]));
}

__device__ __forceinline__ float gelu_exact(float v) {
    return 0.5f * v * (1.0f + erff(v * 0.70710678118654752f));
}
struct __align__(8) bf4 { bf16 a, b, c, d; };
struct __align__(4) bf2 { bf16 a, b; };

__device__ __forceinline__ uint32_t packbf2(float a, float b) {
    __nv_bfloat162 t = __float22bfloat162_rn(make_float2(a, b));
    return *(uint32_t*)&t;
}

// ---------------- LayerNorm -> bf16 hi/lo split -------------------------------
__global__ void __launch_bounds__(256) ln_split(const float* __restrict__ x,
                                                const float* __restrict__ g,
                                                const float* __restrict__ beta,
                                                bf16* __restrict__ hi,
                                                bf16* __restrict__ lo)
{
    int row = blockIdx.x;
    int t   = threadIdx.x;
    float4 xv = ((const float4*)(x + (size_t)row * Dsz))[t];
    float s  = xv.x + xv.y + xv.z + xv.w;
    float ss = xv.x*xv.x + xv.y*xv.y + xv.z*xv.z + xv.w*xv.w;
    #pragma unroll
    for (int o = 16; o; o >>= 1) {
        s  += __shfl_xor_sync(0xffffffffu, s,  o);
        ss += __shfl_xor_sync(0xffffffffu, ss, o);
    }
    __shared__ float sh[16];
    int w = t >> 5;
    if ((t & 31) == 0) { sh[w] = s; sh[8 + w] = ss; }
    __syncthreads();
    s = 0.f; ss = 0.f;
    #pragma unroll
    for (int i = 0; i < 8; i++) { s += sh[i]; ss += sh[8 + i]; }
    float mu  = s * (1.0f / Dsz);
    float var = ss * (1.0f / Dsz) - mu * mu;
    float inv = rsqrtf(var + 1e-5f);
    float4 gv = ((const float4*)g)[t];
    float4 bv = ((const float4*)beta)[t];
    float r[4];
    r[0] = (xv.x - mu) * inv * gv.x + bv.x;
    r[1] = (xv.y - mu) * inv * gv.y + bv.y;
    r[2] = (xv.z - mu) * inv * gv.z + bv.z;
    r[3] = (xv.w - mu) * inv * gv.w + bv.w;
    bf16 h4[4], l4[4];
    #pragma unroll
    for (int i = 0; i < 4; i++) {
        h4[i] = __float2bfloat16_rn(r[i]);
        l4[i] = __float2bfloat16_rn(r[i] - __bfloat162float(h4[i]));
    }
    size_t off = (size_t)row * Dsz + t * 4;
    *(bf4*)(hi + off) = bf4{h4[0], h4[1], h4[2], h4[3]};
    *(bf4*)(lo + off) = bf4{l4[0], l4[1], l4[2], l4[3]};
}

// ---------------- transpose + split: in[Kd, segN] -> out[rowBase+n][Kd] --------
__device__ __forceinline__ void trans_split_body(const float* __restrict__ ib,
                                                 bf16* __restrict__ oh,
                                                 bf16* __restrict__ ol,
                                                 int Kd, int segN,
                                                 int k0, int n0, size_t rowBase,
                                                 int tx, int ty, float s[32][33])
{
    #pragma unroll
    for (int ii = 0; ii < 4; ii++)
        s[ty + ii * 8][tx] = ib[(size_t)(k0 + ty + ii * 8) * segN + n0 + tx];
    __syncthreads();
    #pragma unroll
    for (int ii = 0; ii < 4; ii++) {
        int n = n0 + ty + ii * 8;
        float v = s[tx][ty + ii * 8];
        bf16 h = __float2bfloat16_rn(v);
        bf16 l = __float2bfloat16_rn(v - __bfloat162float(h));
        size_t o = (rowBase + n) * (size_t)Kd + k0 + tx;
        oh[o] = h; ol[o] = l;
    }
}

__global__ void __launch_bounds__(256) trans_split(const float* __restrict__ in,
                                                   bf16* __restrict__ oh,
                                                   bf16* __restrict__ ol,
                                                   int Kd, int segN)
{
    __shared__ float s[32][33];
    int k0 = blockIdx.x * 32, n0 = blockIdx.y * 32, z = blockIdx.z;
    trans_split_body(in + (size_t)z * Kd * segN, oh, ol, Kd, segN,
                     k0, n0, (size_t)z * segN,
                     threadIdx.x & 31, threadIdx.x >> 5, s);
}

// fused QKV weight prep: z in [0,48): seg = z>>4 (q/k/v), head = z&15
__global__ void __launch_bounds__(256) trans_split_qkv(const float* __restrict__ Wq,
                                                       const float* __restrict__ Wk,
                                                       const float* __restrict__ Wv,
                                                       bf16* __restrict__ oh,
                                                       bf16* __restrict__ ol)
{
    __shared__ float s[32][33];
    int k0 = blockIdx.x * 32, n0 = blockIdx.y * 32, z = blockIdx.z;
    int seg = z >> 4, head = z & 15;
    const float* W = (seg == 0) ? Wq : (seg == 1) ? Wk : Wv;
    trans_split_body(W + (size_t)head * Dsz * DHsz,
                     oh + (size_t)seg * Dsz * Dsz, ol + (size_t)seg * Dsz * Dsz,
                     Dsz, DHsz, k0, n0, (size_t)head * DHsz,
                     threadIdx.x & 31, threadIdx.x >> 5, s);
}

// ---------------- mma.sync GEMM, bf16-split 3-pass (round-7 proven config) -----
// 128x128 CTA tile, 8 warps (4m x 2n), warp tile 32x64, K-slab 32, 2-stage.
// __launch_bounds__(256,2) forces <=128 regs -> guaranteed 2 CTAs/SM.
#define MATB   10240
#define STAGEB (4*MATB)
#define GSMEM  (2*STAGEB)   // 81920

template<int MODE>
__global__ void __launch_bounds__(256, 2) gemm_mma(
    const bf16* __restrict__ Ahi, const bf16* __restrict__ Alo,
    const bf16* __restrict__ Bhi, const bf16* __restrict__ Blo,
    const float* __restrict__ bias,          // MODE 1/2; MODE 0: q bias
    const float* __restrict__ biasK,         // MODE 0 only
    const float* __restrict__ biasV,         // MODE 0 only
    float* __restrict__ O0,
    bf16* __restrict__ OH, bf16* __restrict__ OL,
    bf16* __restrict__ Qh, bf16* __restrict__ Ql,
    bf16* __restrict__ Kh, bf16* __restrict__ Kl,
    bf16* __restrict__ Vh, bf16* __restrict__ Vl,
    int N, int K)
{
    extern __shared__ __align__(1024) char smem[];
    uint32_t sb = smem_u32(smem);
    int tid = threadIdx.x, wid = tid >> 5, lane = tid & 31;
    int m0 = blockIdx.y * 128, n0 = blockIdx.x * 128;
    int wm = (wid & 3) * 32, wn = (wid >> 2) * 64;

    const char* gbase[4] = {
        (const char*)(Ahi + (size_t)m0 * K),
        (const char*)(Alo + (size_t)m0 * K),
        (const char*)(Bhi + (size_t)n0 * K),
        (const char*)(Blo + (size_t)n0 * K)};
    const size_t ldb = (size_t)K * 2;

    const int lrow = tid >> 1;           // 0..127
    const int lcc  = (tid & 1) * 32;     // byte col within 64B slab row

    float acc[2][8][4];
    #pragma unroll
    for (int t = 0; t < 2; t++)
        #pragma unroll
        for (int j = 0; j < 8; j++)
            #pragma unroll
            for (int q = 0; q < 4; q++) acc[t][j][q] = 0.f;

    int nslab = K >> 5;

    // ---- prologue: load stage 0
    {
        uint32_t stg = sb;
        #pragma unroll
        for (int mat = 0; mat < 4; mat++) {
            const char* g = gbase[mat] + (size_t)lrow * ldb + lcc;
            uint32_t dst = stg + mat * MATB + lrow * 80 + lcc;
            cp16(dst, g); cp16(dst + 16, g + 16);
        }
        cp_commit();
    }

    const int arow = lane & 15;
    const int akh  = (lane >> 4) * 16;
    const int bn   = ((lane >> 4) & 1) * 8 + (lane & 7);
    const int bkh  = ((lane >> 3) & 1) * 16;

    for (int s = 0; s < nslab; ++s) {
        uint32_t stg = sb + (s & 1) * STAGEB;
        if (s + 1 < nslab) {
            uint32_t nstg = sb + ((s + 1) & 1) * STAGEB;
            #pragma unroll
            for (int mat = 0; mat < 4; mat++) {
                const char* g = gbase[mat] + (size_t)lrow * ldb + (size_t)(s + 1) * 64 + lcc;
                uint32_t dst = nstg + mat * MATB + lrow * 80 + lcc;
                cp16(dst, g); cp16(dst + 16, g + 16);
            }
            cp_commit();
            cp_wait1();
        } else {
            cp_wait0();
        }
        __syncthreads();

        #pragma unroll
        for (int ks = 0; ks < 2; ks++) {
            int kb = ks * 32;
            uint32_t ah[8], al[8];
            #pragma unroll
            for (int t = 0; t < 2; t++) {
                uint32_t ra = stg + (wm + t * 16 + arow) * 80 + kb + akh;
                ldsm4(&ah[t * 4], ra);
                ldsm4(&al[t * 4], ra + MATB);
            }
            #pragma unroll
            for (int p = 0; p < 4; p++) {
                uint32_t rb = stg + 2 * MATB + (wn + p * 16 + bn) * 80 + kb + bkh;
                uint32_t bh[4], bl[4];
                ldsm4(bh, rb);
                ldsm4(bl, rb + MATB);
                #pragma unroll
                for (int t = 0; t < 2; t++) {
                    mma_bf16(acc[t][p*2+0], &ah[t*4], &bh[0]);
                    mma_bf16(acc[t][p*2+1], &ah[t*4], &bh[2]);
                    mma_bf16(acc[t][p*2+0], &ah[t*4], &bl[0]);
                    mma_bf16(acc[t][p*2+1], &ah[t*4], &bl[2]);
                    mma_bf16(acc[t][p*2+0], &al[t*4], &bh[0]);
                    mma_bf16(acc[t][p*2+1], &al[t*4], &bh[2]);
                }
            }
        }
        __syncthreads();
    }

    // ---- epilogue: direct fragment stores
    int g2 = lane >> 2, c2 = (lane & 3) * 2;
    #pragma unroll
    for (int t = 0; t < 2; t++) {
        #pragma unroll
        for (int j = 0; j < 8; j++) {
            int m = m0 + wm + t * 16 + g2;
            int n = n0 + wn + j * 8 + c2;
            float b0, b1;
            if (MODE == 0) {
                const float* bsel = (n < 1024) ? bias : (n < 2048) ? biasK : biasV;
                b0 = bsel[n & 1023]; b1 = bsel[(n & 1023) + 1];
            } else {
                b0 = bias[n]; b1 = bias[n + 1];
            }
            float v00 = acc[t][j][0] + b0, v01 = acc[t][j][1] + b1;
            float v10 = acc[t][j][2] + b0, v11 = acc[t][j][3] + b1;
            if (MODE == 0) {
                int which = n >> 10, hh = (n >> 6) & 15, e = n & 63;
                int b_ = m >> 11, s0 = m & 2047;
                bf16 h00 = __float2bfloat16_rn(v00), h01 = __float2bfloat16_rn(v01);
                bf16 h10 = __float2bfloat16_rn(v10), h11 = __float2bfloat16_rn(v11);
                bf16 l00 = __float2bfloat16_rn(v00 - __bfloat162float(h00));
                bf16 l01 = __float2bfloat16_rn(v01 - __bfloat162float(h01));
                bf16 l10 = __float2bfloat16_rn(v10 - __bfloat162float(h10));
                bf16 l11 = __float2bfloat16_rn(v11 - __bfloat162float(h11));
                if (which < 2) {
                    bf16* dh_ = (which == 0) ? Qh : Kh;
                    bf16* dl_ = (which == 0) ? Ql : Kl;
                    size_t base = ((size_t)(b_ * Hsz + hh) * Ssz + s0) * 64 + e;
                    *(bf2*)&dh_[base] = bf2{h00, h01};
                    *(bf2*)&dl_[base] = bf2{l00, l01};
                    *(bf2*)&dh_[base + 8 * 64] = bf2{h10, h11};
                    *(bf2*)&dl_[base + 8 * 64] = bf2{l10, l11};
                } else {
                    size_t base = ((size_t)(b_ * Hsz + hh) * 64 + e) * Ssz + s0;
                    Vh[base]            = h00;  Vl[base]            = l00;
                    Vh[base + Ssz]      = h01;  Vl[base + Ssz]      = l01;
                    Vh[base + 8]        = h10;  Vl[base + 8]        = l10;
                    Vh[base + Ssz + 8]  = h11;  Vl[base + Ssz + 8]  = l11;
                }
            } else if (MODE == 1) {
                v00 = gelu_exact(v00); v01 = gelu_exact(v01);
                v10 = gelu_exact(v10); v11 = gelu_exact(v11);
                bf16 h00 = __float2bfloat16_rn(v00), h01 = __float2bfloat16_rn(v01);
                bf16 h10 = __float2bfloat16_rn(v10), h11 = __float2bfloat16_rn(v11);
                bf16 l00 = __float2bfloat16_rn(v00 - __bfloat162float(h00));
                bf16 l01 = __float2bfloat16_rn(v01 - __bfloat162float(h01));
                bf16 l10 = __float2bfloat16_rn(v10 - __bfloat162float(h10));
                bf16 l11 = __float2bfloat16_rn(v11 - __bfloat162float(h11));
                size_t r0 = (size_t)m * N + n, r1 = (size_t)(m + 8) * N + n;
                *(bf2*)&OH[r0] = bf2{h00, h01};
                *(bf2*)&OH[r1] = bf2{h10, h11};
                *(bf2*)&OL[r0] = bf2{l00, l01};
                *(bf2*)&OL[r1] = bf2{l10, l11};
            } else {
                size_t r0 = (size_t)m * N + n, r1 = (size_t)(m + 8) * N + n;
                float2 c0 = *(float2*)&O0[r0];
                float2 c1 = *(float2*)&O0[r1];
                *(float2*)&O0[r0] = make_float2(v00 + c0.x, v01 + c0.y);
                *(float2*)&O0[r1] = make_float2(v10 + c1.x, v11 + c1.y);
            }
        }
    }
}

// ---------------- tensor-core flash attention (causal) -------------------------
// Round-16 best + K-issue hoisted above the loop-top sync (K writes sK, whose
// last readers all passed the prior mid-tile barrier; only V-issue must wait
// for PV readers of sV). Same syncs/tile, K load launches earlier.
#define AMAT 9216
#define ASMEM (6*AMAT)   // Qh Ql Kh Kl Vth Vtl = 55296

__global__ void __launch_bounds__(128, 3) attn_mma(
    const bf16* __restrict__ qh, const bf16* __restrict__ ql,
    const bf16* __restrict__ kh, const bf16* __restrict__ kl,
    const bf16* __restrict__ vth, const bf16* __restrict__ vtl,
    const float* __restrict__ x, float* __restrict__ out)
{
    extern __shared__ __align__(1024) char asmem[];
    uint32_t sb = smem_u32(asmem);
    const uint32_t sQh = sb, sKh = sb + 2*AMAT, sVh = sb + 4*AMAT;

    int tid = threadIdx.x, lane = tid & 31, wid = tid >> 5;
    int bh = blockIdx.y;
    int qt = gridDim.x - 1 - blockIdx.x;
    int q0 = qt * 64;
    int wm = wid * 16;

    const bf16* qhg = qh + ((size_t)bh * Ssz + q0) * 64;
    const bf16* qlg = ql + ((size_t)bh * Ssz + q0) * 64;
    const bf16* khg = kh + (size_t)bh * Ssz * 64;
    const bf16* klg = kl + (size_t)bh * Ssz * 64;
    const bf16* vthg = vth + (size_t)bh * 64 * Ssz;
    const bf16* vtlg = vtl + (size_t)bh * 64 * Ssz;

    #pragma unroll
    for (int i = 0; i < 4; i++) {
        int ch = i * 128 + tid;
        int r = ch >> 3, c = (ch & 7) * 16;
        cp16(sQh + r * 144 + c, (const char*)qhg + r * 128 + c);
        cp16(sQh + AMAT + r * 144 + c, (const char*)qlg + r * 128 + c);
    }
    cp_commit(); cp_wait0(); __syncthreads();

    const int arow = lane & 15;
    const int akh  = (lane >> 4) * 16;
    const int bn   = ((lane >> 4) & 1) * 8 + (lane & 7);
    const int bkh  = ((lane >> 3) & 1) * 16;

    uint32_t qfh[4][4], qfl[4][4];
    #pragma unroll
    for (int kc = 0; kc < 4; kc++) {
        uint32_t a = sQh + (wm + arow) * 144 + kc * 32 + akh;
        ldsm4(qfh[kc], a);
        ldsm4(qfl[kc], a + AMAT);
    }

    float m0 = -1e30f, m1 = -1e30f, l0 = 0.f, l1 = 0.f;
    float o[4][2][4];
    #pragma unroll
    for (int pd = 0; pd < 4; pd++)
        #pragma unroll
        for (int f = 0; f < 2; f++)
            #pragma unroll
            for (int e = 0; e < 4; e++) o[pd][f][e] = 0.f;

    int r0g = q0 + wm + (lane >> 2);
    int ntiles = qt + 1;

    for (int t = 0; t < ntiles; t++) {
        int j0 = t * 64;
        // K group: sK has no outstanding readers (S phase of prior tile completed
        // before the prior mid-tile barrier) -> issue before the sync.
        #pragma unroll
        for (int i = 0; i < 4; i++) {
            int ch = i * 128 + tid;
            int r = ch >> 3, c = (ch & 7) * 16;
            cp16(sKh + r * 144 + c,        (const char*)(khg + (size_t)(j0 + r) * 64) + c);
            cp16(sKh + AMAT + r * 144 + c, (const char*)(klg + (size_t)(j0 + r) * 64) + c);
        }
        cp_commit();
        __syncthreads();   // all warps done with prior PV (sV readers) before V refill
        // V group (in flight during S/softmax)
        #pragma unroll
        for (int i = 0; i < 4; i++) {
            int ch = i * 128 + tid;
            int r = ch >> 3, c = (ch & 7) * 16;
            cp16(sVh + r * 144 + c,        (const char*)(vthg + (size_t)r * Ssz + j0) + c);
            cp16(sVh + AMAT + r * 144 + c, (const char*)(vtlg + (size_t)r * Ssz + j0) + c);
        }
        cp_commit();
        cp_wait1();        // K resident; V may still fly
        __syncthreads();

        float s[4][2][4];
        #pragma unroll
        for (int p = 0; p < 4; p++)
            #pragma unroll
            for (int f = 0; f < 2; f++)
                #pragma unroll
                for (int e = 0; e < 4; e++) s[p][f][e] = 0.f;

        #pragma unroll
        for (int kc = 0; kc < 4; kc++) {
            #pragma unroll
            for (int p = 0; p < 4; p++) {
                uint32_t kf[4], kg[4];
                uint32_t a = sKh + (p * 16 + bn) * 144 + kc * 32 + bkh;
                ldsm4(kf, a);
                ldsm4(kg, a + AMAT);
                mma_bf16(s[p][0], qfh[kc], &kf[0]);
                mma_bf16(s[p][1], qfh[kc], &kf[2]);
                mma_bf16(s[p][0], qfh[kc], &kg[0]);
                mma_bf16(s[p][1], qfh[kc], &kg[2]);
                mma_bf16(s[p][0], qfl[kc], &kf[0]);
                mma_bf16(s[p][1], qfl[kc], &kf[2]);
            }
        }

        bool diag = (j0 == q0);
        #pragma unroll
        for (int p = 0; p < 4; p++)
            #pragma unroll
            for (int f = 0; f < 2; f++) {
                int colb = j0 + p * 16 + f * 8 + (lane & 3) * 2;
                #pragma unroll
                for (int e = 0; e < 4; e++) {
                    float sv = s[p][f][e] * 0.125f;
                    if (diag) {
                        int col = colb + (e & 1);
                        int row = r0g + ((e >> 1) << 3);
                        if (col > row) sv = -1e30f;
                    }
                    s[p][f][e] = sv;
                }
            }

        float rx0 = -1e30f, rx1 = -1e30f;
        #pragma unroll
        for (int p = 0; p < 4; p++)
            #pragma unroll
            for (int f = 0; f < 2; f++) {
                rx0 = fmaxf(rx0, fmaxf(s[p][f][0], s[p][f][1]));
                rx1 = fmaxf(rx1, fmaxf(s[p][f][2], s[p][f][3]));
            }
        rx0 = fmaxf(rx0, __shfl_xor_sync(0xffffffffu, rx0, 1));
        rx0 = fmaxf(rx0, __shfl_xor_sync(0xffffffffu, rx0, 2));
        rx1 = fmaxf(rx1, __shfl_xor_sync(0xffffffffu, rx1, 1));
        rx1 = fmaxf(rx1, __shfl_xor_sync(0xffffffffu, rx1, 2));
        float mn0 = fmaxf(m0, rx0), mn1 = fmaxf(m1, rx1);
        float a0 = __expf(m0 - mn0), a1 = __expf(m1 - mn1);
        m0 = mn0; m1 = mn1;

        float sum0 = 0.f, sum1 = 0.f;
        #pragma unroll
        for (int p = 0; p < 4; p++)
            #pragma unroll
            for (int f = 0; f < 2; f++) {
                float p0 = __expf(s[p][f][0] - mn0);
                float p1 = __expf(s[p][f][1] - mn0);
                float p2 = __expf(s[p][f][2] - mn1);
                float p3 = __expf(s[p][f][3] - mn1);
                s[p][f][0] = p0; s[p][f][1] = p1; s[p][f][2] = p2; s[p][f][3] = p3;
                sum0 += p0 + p1; sum1 += p2 + p3;
            }
        sum0 += __shfl_xor_sync(0xffffffffu, sum0, 1);
        sum0 += __shfl_xor_sync(0xffffffffu, sum0, 2);
        sum1 += __shfl_xor_sync(0xffffffffu, sum1, 1);
        sum1 += __shfl_xor_sync(0xffffffffu, sum1, 2);
        l0 = l0 * a0 + sum0;
        l1 = l1 * a1 + sum1;
        #pragma unroll
        for (int pd = 0; pd < 4; pd++)
            #pragma unroll
            for (int f = 0; f < 2; f++) {
                o[pd][f][0] *= a0; o[pd][f][1] *= a0;
                o[pd][f][2] *= a1; o[pd][f][3] *= a1;
            }

        cp_wait0();        // V resident
        __syncthreads();

        #pragma unroll
        for (int kc = 0; kc < 4; kc++) {
            uint32_t pah[4], pal[4];
            #pragma unroll
            for (int f = 0; f < 2; f++) {
                float x0 = s[kc][f][0], x1 = s[kc][f][1];
                float x2 = s[kc][f][2], x3 = s[kc][f][3];
                uint32_t h01 = packbf2(x0, x1);
                uint32_t h23 = packbf2(x2, x3);
                __nv_bfloat162 hb01 = *(__nv_bfloat162*)&h01;
                __nv_bfloat162 hb23 = *(__nv_bfloat162*)&h23;
                uint32_t lo01 = packbf2(x0 - __bfloat162float(hb01.x),
                                        x1 - __bfloat162float(hb01.y));
                uint32_t lo23 = packbf2(x2 - __bfloat162float(hb23.x),
                                        x3 - __bfloat162float(hb23.y));
                pah[f * 2 + 0] = h01;  pal[f * 2 + 0] = lo01;
                pah[f * 2 + 1] = h23;  pal[f * 2 + 1] = lo23;
            }
            #pragma unroll
            for (int pd = 0; pd < 4; pd++) {
                uint32_t vf[4], vg[4];
                uint32_t a = sVh + (pd * 16 + bn) * 144 + kc * 32 + bkh;
                ldsm4(vf, a);
                ldsm4(vg, a + AMAT);
                mma_bf16(o[pd][0], pah, &vf[0]);
                mma_bf16(o[pd][1], pah, &vf[2]);
                mma_bf16(o[pd][0], pah, &vg[0]);
                mma_bf16(o[pd][1], pah, &vg[2]);
                mma_bf16(o[pd][0], pal, &vf[0]);
                mma_bf16(o[pd][1], pal, &vf[2]);
            }
        }
    }

    float inv0 = 1.0f / l0, inv1 = 1.0f / l1;
    int b_ = bh >> 4, hh = bh & 15;
    #pragma unroll
    for (int pd = 0; pd < 4; pd++)
        #pragma unroll
        for (int f = 0; f < 2; f++) {
            int dh = pd * 16 + f * 8 + (lane & 3) * 2;
            size_t i0 = ((size_t)(b_ * Ssz + r0g)) * Dsz + hh * 64 + dh;
            size_t i1 = i0 + (size_t)8 * Dsz;
            float2 x0 = *(const float2*)&x[i0];
            float2 x1 = *(const float2*)&x[i1];
            *(float2*)&out[i0] = make_float2(x0.x + o[pd][f][0] * inv0,
                                             x0.y + o[pd][f][1] * inv0);
            *(float2*)&out[i1] = make_float2(x1.x + o[pd][f][2] * inv1,
                                             x1.y + o[pd][f][3] * inv1);
        }
}

// ---------------- launch --------------------------------------------------------
extern "C" void kernel_launch(void* const* d_in, const int* in_sizes, int n_in,
                              void* d_out, int out_size)
{
    const float* x    = (const float*)d_in[0];
    const float* Wq   = (const float*)d_in[1];
    const float* bq   = (const float*)d_in[2];
    const float* Wk   = (const float*)d_in[3];
    const float* bk   = (const float*)d_in[4];
    const float* Wv   = (const float*)d_in[5];
    const float* bv   = (const float*)d_in[6];
    const float* ln1g = (const float*)d_in[7];
    const float* ln1b = (const float*)d_in[8];
    const float* ln2g = (const float*)d_in[9];
    const float* ln2b = (const float*)d_in[10];
    const float* W1   = (const float*)d_in[11];
    const float* b1   = (const float*)d_in[12];
    const float* W2   = (const float*)d_in[13];
    const float* b2   = (const float*)d_in[14];
    float* out = (float*)d_out;

    bf16 *hhi, *hlo, *midhi, *midlo, *wqkvh, *wqkvl, *w1h, *w1l, *w2h, *w2l;
    bf16 *qh_, *ql_, *kh_, *kl_, *vth_, *vtl_;
    cudaGetSymbolAddress((void**)&hhi,   g_hhi);
    cudaGetSymbolAddress((void**)&hlo,   g_hlo);
    cudaGetSymbolAddress((void**)&midhi, g_midhi);
    cudaGetSymbolAddress((void**)&midlo, g_midlo);
    cudaGetSymbolAddress((void**)&wqkvh, g_wqkvT_hi);
    cudaGetSymbolAddress((void**)&wqkvl, g_wqkvT_lo);
    cudaGetSymbolAddress((void**)&w1h,   g_w1T_hi);
    cudaGetSymbolAddress((void**)&w1l,   g_w1T_lo);
    cudaGetSymbolAddress((void**)&w2h,   g_w2T_hi);
    cudaGetSymbolAddress((void**)&w2l,   g_w2T_lo);
    cudaGetSymbolAddress((void**)&qh_,   g_qh);
    cudaGetSymbolAddress((void**)&ql_,   g_ql);
    cudaGetSymbolAddress((void**)&kh_,   g_kh);
    cudaGetSymbolAddress((void**)&kl_,   g_kl);
    cudaGetSymbolAddress((void**)&vth_,  g_vth);
    cudaGetSymbolAddress((void**)&vtl_,  g_vtl);

    cudaFuncSetAttribute(gemm_mma<0>, cudaFuncAttributeMaxDynamicSharedMemorySize, GSMEM);
    cudaFuncSetAttribute(gemm_mma<1>, cudaFuncAttributeMaxDynamicSharedMemorySize, GSMEM);
    cudaFuncSetAttribute(gemm_mma<2>, cudaFuncAttributeMaxDynamicSharedMemorySize, GSMEM);
    cudaFuncSetAttribute(attn_mma, cudaFuncAttributeMaxDynamicSharedMemorySize, ASMEM);

    // weight prep (tight grids: QKV fused, W1, W2)
    trans_split_qkv<<<dim3(Dsz/32, DHsz/32, 48), 256>>>(Wq, Wk, Wv, wqkvh, wqkvl);
    trans_split<<<dim3(Dsz/32, FFsz/32, 1),  256>>>(W1, w1h, w1l, Dsz, FFsz);
    trans_split<<<dim3(FFsz/32, Dsz/32, 1),  256>>>(W2, w2h, w2l, FFsz, Dsz);

    // 1) LN1 -> bf16 split
    ln_split<<<Mrows, 256>>>(x, ln1g, ln1b, hhi, hlo);

    // 2) fused QKV GEMM (N = 3072) -> bf16 q/k + transposed v (bias selected inline)
    gemm_mma<0><<<dim3(3*Dsz/128, Mrows/128), 256, GSMEM>>>(
        hhi, hlo, wqkvh, wqkvl, bq, bk, bv, nullptr, nullptr, nullptr,
        qh_, ql_, kh_, kl_, vth_, vtl_, 3*Dsz, Dsz);

    // 3) tensor-core attention + residual -> out = x1
    attn_mma<<<dim3(Ssz/64, BH), 128, ASMEM>>>(qh_, ql_, kh_, kl_, vth_, vtl_, x, out);

    // 4) LN2 -> bf16 split
    ln_split<<<Mrows, 256>>>(out, ln2g, ln2b, hhi, hlo);

    // 5) mid = GELU(h @ W1 + b1), split to bf16
    gemm_mma<1><<<dim3(FFsz/128, Mrows/128), 256, GSMEM>>>(
        hhi, hlo, w1h, w1l, b1, nullptr, nullptr, nullptr, midhi, midlo,
        nullptr, nullptr, nullptr, nullptr, nullptr, nullptr, FFsz, Dsz);

    // 6) out = x1 + mid @ W2 + b2
    gemm_mma<2><<<dim3(Dsz/128, Mrows/128), 256, GSMEM>>>(
        midhi, midlo, w2h, w2l, b2, nullptr, nullptr, out, nullptr, nullptr,
        nullptr, nullptr, nullptr, nullptr, nullptr, nullptr, Dsz, FFsz);
}